// round 1
// baseline (speedup 1.0000x reference)
#include <cuda_runtime.h>
#include <cuda_bf16.h>

// ---------------- problem constants ----------------
#define BW   64            // windows (batch)
#define NT   512           // tokens per window (8^3)
#define CC   192           // channels
#define HH   6             // heads
#define HD   32            // head dim
#define NWIN 16            // mask windows
#define TBL  3375          // (2*8-1)^3

// ---------------- device scratch ----------------
__device__ float g_tbl[TBL * HH];                  // 16*sigmoid(cpb table)
__device__ float g_bias[HH * NT * NT];             // [h][i][j]  6 MB
__device__ float g_q[BW * HH * NT * HD];           // [b][h][n][d]
__device__ float g_k[BW * HH * NT * HD];
__device__ float g_v[BW * HH * NT * HD];
__device__ float g_att[BW * NT * CC];              // attention out, [b*n][c]

// ---------------- 1. CPB MLP ----------------
__global__ void cpb_kernel(const float* __restrict__ tb, const float* __restrict__ w1,
                           const float* __restrict__ b1, const float* __restrict__ w2) {
    int r = blockIdx.x;
    float c0 = tb[r * 3 + 0], c1 = tb[r * 3 + 1], c2 = tb[r * 3 + 2];
    float acc[HH] = {0.f, 0.f, 0.f, 0.f, 0.f, 0.f};
    for (int j = threadIdx.x; j < 512; j += 128) {
        float hv = fmaf(c0, w1[j * 3 + 0], fmaf(c1, w1[j * 3 + 1], fmaf(c2, w1[j * 3 + 2], b1[j])));
        hv = fmaxf(hv, 0.f);
#pragma unroll
        for (int h = 0; h < HH; h++) acc[h] = fmaf(hv, w2[h * 512 + j], acc[h]);
    }
    __shared__ float red[HH][128];
#pragma unroll
    for (int h = 0; h < HH; h++) red[h][threadIdx.x] = acc[h];
    __syncthreads();
    for (int s = 64; s > 0; s >>= 1) {
        if (threadIdx.x < s) {
#pragma unroll
            for (int h = 0; h < HH; h++) red[h][threadIdx.x] += red[h][threadIdx.x + s];
        }
        __syncthreads();
    }
    if (threadIdx.x < HH) {
        float v = red[threadIdx.x][0];
        g_tbl[r * HH + threadIdx.x] = 16.f / (1.f + __expf(-v));
    }
}

// ---------------- 2. bias gather ----------------
__global__ void gather_kernel(const int* __restrict__ rel_index) {
    int ij = blockIdx.x * 256 + threadIdx.x;   // i*512 + j
    int id = rel_index[ij];
#pragma unroll
    for (int h = 0; h < HH; h++)
        g_bias[h * (NT * NT) + ij] = g_tbl[id * HH + h];
}

// ---------------- 3/6. NT GEMM: C[m][n] = sum_k A[m][k]*B[n][k] (+bias) ----------------
// MODE 0: A=x [32768,192], B=qkv_w [576,192], scatter into g_q/g_k/g_v with (q_bias,0,v_bias)
// MODE 1: A=g_att [32768,192], B=proj_w [192,192], out=Cout with proj_b
template <int MODE>
__global__ void __launch_bounds__(256) gemm_nt(const float* __restrict__ A,
                                               const float* __restrict__ Bw,
                                               const float* __restrict__ bias0,
                                               const float* __restrict__ bias2,
                                               float* __restrict__ Cout) {
    __shared__ float As[16][68];
    __shared__ float Bs[16][68];
    const int tid = threadIdx.x;
    const int tx = tid & 15, ty = tid >> 4;
    const int m0 = blockIdx.y * 64;
    const int n0 = blockIdx.x * 64;
    const float* Aptr = (MODE == 0) ? A : g_att;

    float acc[4][4];
#pragma unroll
    for (int i = 0; i < 4; i++)
#pragma unroll
        for (int j = 0; j < 4; j++) acc[i][j] = 0.f;

    const int lr = tid >> 2;          // 0..63 row within tile
    const int lk = (tid & 3) * 4;     // k quad
    const float* Ag = Aptr + (m0 + lr) * 192 + lk;
    const float* Bg = Bw + (n0 + lr) * 192 + lk;

    for (int kt = 0; kt < 192; kt += 16) {
        float4 av = *(const float4*)(Ag + kt);
        float4 bv = *(const float4*)(Bg + kt);
        __syncthreads();
        As[lk + 0][lr] = av.x; As[lk + 1][lr] = av.y; As[lk + 2][lr] = av.z; As[lk + 3][lr] = av.w;
        Bs[lk + 0][lr] = bv.x; Bs[lk + 1][lr] = bv.y; Bs[lk + 2][lr] = bv.z; Bs[lk + 3][lr] = bv.w;
        __syncthreads();
#pragma unroll
        for (int kk = 0; kk < 16; kk++) {
            float4 a4 = *(const float4*)(&As[kk][ty * 4]);
            float4 b4 = *(const float4*)(&Bs[kk][tx * 4]);
            float a[4] = {a4.x, a4.y, a4.z, a4.w};
            float b[4] = {b4.x, b4.y, b4.z, b4.w};
#pragma unroll
            for (int i = 0; i < 4; i++)
#pragma unroll
                for (int j = 0; j < 4; j++) acc[i][j] = fmaf(a[i], b[j], acc[i][j]);
        }
    }

    const int n = n0 + tx * 4;
    if (MODE == 0) {
        const int s = n / 192;
        const int rem = n - s * 192;
        const int h = rem >> 5;
        const int d = rem & 31;
        float bad[4];
#pragma unroll
        for (int u = 0; u < 4; u++)
            bad[u] = (s == 0) ? bias0[rem + u] : ((s == 2) ? bias2[rem + u] : 0.f);
        float* base = (s == 0) ? g_q : ((s == 1) ? g_k : g_v);
#pragma unroll
        for (int i = 0; i < 4; i++) {
            int m = m0 + ty * 4 + i;
            int bb = m >> 9, nr = m & 511;
            float4 v = make_float4(acc[i][0] + bad[0], acc[i][1] + bad[1],
                                   acc[i][2] + bad[2], acc[i][3] + bad[3]);
            *(float4*)(base + (((bb * HH + h) << 9) + nr) * HD + d) = v;
        }
    } else {
        float4 pb = *(const float4*)(bias0 + n);
#pragma unroll
        for (int i = 0; i < 4; i++) {
            int m = m0 + ty * 4 + i;
            float4 v = make_float4(acc[i][0] + pb.x, acc[i][1] + pb.y,
                                   acc[i][2] + pb.z, acc[i][3] + pb.w);
            *(float4*)(Cout + m * 192 + n) = v;
        }
    }
}

// ---------------- 4. normalize q,k (fold logit scale into q) ----------------
__global__ void norm_kernel(const float* __restrict__ logit_scale) {
    int warp = threadIdx.x >> 5, lane = threadIdx.x & 31;
    int r = blockIdx.x * 8 + warp;             // row in [0, 64*6*512)
    int h = (r >> 9) % HH;
    float sc = __expf(fminf(logit_scale[h], 4.6051702f));   // ln(100)
    float qv = g_q[r * HD + lane];
    float kv = g_k[r * HD + lane];
    float qs = qv * qv, ks = kv * kv;
#pragma unroll
    for (int o = 16; o > 0; o >>= 1) {
        qs += __shfl_xor_sync(0xffffffffu, qs, o);
        ks += __shfl_xor_sync(0xffffffffu, ks, o);
    }
    g_q[r * HD + lane] = qv * (sc / fmaxf(sqrtf(qs), 1e-12f));
    g_k[r * HD + lane] = kv / fmaxf(sqrtf(ks), 1e-12f);
}

// ---------------- 5. fp32 flash attention ----------------
__global__ void __launch_bounds__(128) attn_kernel(const float* __restrict__ mask) {
    const int b = blockIdx.z, h = blockIdx.y;
    const int i = blockIdx.x * 128 + threadIdx.x;
    const int w = b & (NWIN - 1);
    __shared__ float Ks[32][36];
    __shared__ float Vs[32][36];

    float4 q4[8];
    const float4* qp = (const float4*)(g_q + (((b * HH + h) << 9) + i) * HD);
#pragma unroll
    for (int u = 0; u < 8; u++) q4[u] = qp[u];

    const float4* brow = (const float4*)(g_bias + (h << 18) + (i << 9));
    const float4* mrow = (const float4*)(mask + (w << 18) + (i << 9));

    float o[32];
#pragma unroll
    for (int d = 0; d < 32; d++) o[d] = 0.f;
    float mx = -1e30f, l = 0.f;

    const int t = threadIdx.x;
    const int jr = t >> 2, qd = t & 3;
    const float* kbase = g_k + ((b * HH + h) << 9) * HD;
    const float* vbase = g_v + ((b * HH + h) << 9) * HD;

    for (int jt = 0; jt < 16; jt++) {
        __syncthreads();
        const float4* kp = (const float4*)(kbase + (jt * 32 + jr) * HD);
        const float4* vp = (const float4*)(vbase + (jt * 32 + jr) * HD);
        ((float4*)Ks[jr])[qd]     = kp[qd];
        ((float4*)Ks[jr])[qd + 4] = kp[qd + 4];
        ((float4*)Vs[jr])[qd]     = vp[qd];
        ((float4*)Vs[jr])[qd + 4] = vp[qd + 4];
        __syncthreads();

#pragma unroll
        for (int c = 0; c < 4; c++) {
            float s[8];
#pragma unroll
            for (int jj = 0; jj < 8; jj++) {
                const float4* kr = (const float4*)Ks[c * 8 + jj];
                float a = 0.f;
#pragma unroll
                for (int u = 0; u < 8; u++) {
                    float4 kv = kr[u];
                    a = fmaf(q4[u].x, kv.x, a);
                    a = fmaf(q4[u].y, kv.y, a);
                    a = fmaf(q4[u].z, kv.z, a);
                    a = fmaf(q4[u].w, kv.w, a);
                }
                s[jj] = a;
            }
            float4 b0 = brow[jt * 8 + c * 2], b1 = brow[jt * 8 + c * 2 + 1];
            float4 m0 = mrow[jt * 8 + c * 2], m1 = mrow[jt * 8 + c * 2 + 1];
            s[0] += b0.x + m0.x; s[1] += b0.y + m0.y; s[2] += b0.z + m0.z; s[3] += b0.w + m0.w;
            s[4] += b1.x + m1.x; s[5] += b1.y + m1.y; s[6] += b1.z + m1.z; s[7] += b1.w + m1.w;

            float cm = s[0];
#pragma unroll
            for (int jj = 1; jj < 8; jj++) cm = fmaxf(cm, s[jj]);
            float mnew = fmaxf(mx, cm);
            float corr = __expf(mx - mnew);
            mx = mnew;
            l *= corr;
#pragma unroll
            for (int d = 0; d < 32; d++) o[d] *= corr;
#pragma unroll
            for (int jj = 0; jj < 8; jj++) {
                float p = __expf(s[jj] - mnew);
                l += p;
                const float4* vr = (const float4*)Vs[c * 8 + jj];
#pragma unroll
                for (int u = 0; u < 8; u++) {
                    float4 vv = vr[u];
                    o[u * 4 + 0] = fmaf(p, vv.x, o[u * 4 + 0]);
                    o[u * 4 + 1] = fmaf(p, vv.y, o[u * 4 + 1]);
                    o[u * 4 + 2] = fmaf(p, vv.z, o[u * 4 + 2]);
                    o[u * 4 + 3] = fmaf(p, vv.w, o[u * 4 + 3]);
                }
            }
        }
    }

    float inv = 1.0f / l;
    float4* op = (float4*)(g_att + (b * NT + i) * CC + h * HD);
#pragma unroll
    for (int u = 0; u < 8; u++)
        op[u] = make_float4(o[u * 4 + 0] * inv, o[u * 4 + 1] * inv,
                            o[u * 4 + 2] * inv, o[u * 4 + 3] * inv);
}

// ---------------- launch ----------------
extern "C" void kernel_launch(void* const* d_in, const int* in_sizes, int n_in,
                              void* d_out, int out_size) {
    const float* x           = (const float*)d_in[0];
    const float* mask        = (const float*)d_in[1];
    const float* qkv_w       = (const float*)d_in[2];
    const float* q_bias      = (const float*)d_in[3];
    const float* v_bias      = (const float*)d_in[4];
    const float* logit_scale = (const float*)d_in[5];
    const float* cpb_w1      = (const float*)d_in[6];
    const float* cpb_b1      = (const float*)d_in[7];
    const float* cpb_w2      = (const float*)d_in[8];
    const float* proj_w      = (const float*)d_in[9];
    const float* proj_b      = (const float*)d_in[10];
    const int*   rel_index   = (const int*)d_in[12];
    const float* rel_table   = (const float*)d_in[11];
    float* out = (float*)d_out;

    // 1. CPB table (3375 rows)
    cpb_kernel<<<TBL, 128>>>(rel_table, cpb_w1, cpb_b1, cpb_w2);
    // 2. bias gather [6,512,512]
    gather_kernel<<<(NT * NT) / 256, 256>>>(rel_index);
    // 3. QKV gemm + scatter (M=32768, N=576)
    gemm_nt<0><<<dim3(576 / 64, (BW * NT) / 64), 256>>>(x, qkv_w, q_bias, v_bias, nullptr);
    // 4. normalize q,k (196608 rows, 8 rows/block)
    norm_kernel<<<(BW * HH * NT) / 8, 256>>>(logit_scale);
    // 5. attention
    attn_kernel<<<dim3(4, HH, BW), 128>>>(mask);
    // 6. proj gemm (M=32768, N=192)
    gemm_nt<1><<<dim3(192 / 64, (BW * NT) / 64), 256>>>(nullptr, proj_w, proj_b, nullptr, out);
}

// round 3
// speedup vs baseline: 1.1284x; 1.1284x over previous
#include <cuda_runtime.h>
#include <cuda_bf16.h>
#include <cstdint>

// ---------------- problem constants ----------------
#define BW   64
#define NT   512
#define CC   192
#define HH   6
#define HD   32
#define NWIN 16
#define TBL  3375
#define KE   576           // expanded K = 3*192

// ---------------- device scratch ----------------
__device__ float g_tbl[TBL * HH];
__device__ float g_bias[HH * NT * NT];
__device__ float g_q[BW * HH * NT * HD];
__device__ float g_k[BW * HH * NT * HD];
__device__ float g_v[BW * HH * NT * HD];
__device__ __nv_bfloat16 g_xE[(size_t)BW * NT * KE];     // x expanded [hi|hi|lo]
__device__ __nv_bfloat16 g_attE[(size_t)BW * NT * KE];   // attn out expanded [hi|hi|lo]
__device__ __nv_bfloat16 g_wqkvE[3 * CC * KE];           // qkv_w expanded [hi|lo|hi]
__device__ __nv_bfloat16 g_wprojE[CC * KE];              // proj_w expanded [hi|lo|hi]

#define SWZ(o) ((o) ^ (((o) >> 3) & 0x70))

__device__ __forceinline__ uint32_t s2u(const void* p) {
    return (uint32_t)__cvta_generic_to_shared(p);
}
__device__ __forceinline__ void ldsm4(uint32_t& r0, uint32_t& r1, uint32_t& r2, uint32_t& r3,
                                      uint32_t addr) {
    asm volatile("ldmatrix.sync.aligned.m8n8.x4.shared.b16 {%0,%1,%2,%3}, [%4];"
                 : "=r"(r0), "=r"(r1), "=r"(r2), "=r"(r3) : "r"(addr));
}
__device__ __forceinline__ void mma16816(float* c, const uint32_t* a, const uint32_t* b) {
    asm volatile(
        "mma.sync.aligned.m16n8k16.row.col.f32.bf16.bf16.f32 "
        "{%0,%1,%2,%3},{%4,%5,%6,%7},{%8,%9},{%0,%1,%2,%3};"
        : "+f"(c[0]), "+f"(c[1]), "+f"(c[2]), "+f"(c[3])
        : "r"(a[0]), "r"(a[1]), "r"(a[2]), "r"(a[3]), "r"(b[0]), "r"(b[1]));
}

// ---------------- 1. CPB MLP ----------------
__global__ void cpb_kernel(const float* __restrict__ tb, const float* __restrict__ w1,
                           const float* __restrict__ b1, const float* __restrict__ w2) {
    int r = blockIdx.x;
    float c0 = tb[r * 3 + 0], c1 = tb[r * 3 + 1], c2 = tb[r * 3 + 2];
    float acc[HH] = {0.f, 0.f, 0.f, 0.f, 0.f, 0.f};
    for (int j = threadIdx.x; j < 512; j += 128) {
        float hv = fmaf(c0, w1[j * 3 + 0], fmaf(c1, w1[j * 3 + 1], fmaf(c2, w1[j * 3 + 2], b1[j])));
        hv = fmaxf(hv, 0.f);
#pragma unroll
        for (int h = 0; h < HH; h++) acc[h] = fmaf(hv, w2[h * 512 + j], acc[h]);
    }
    __shared__ float red[HH][128];
#pragma unroll
    for (int h = 0; h < HH; h++) red[h][threadIdx.x] = acc[h];
    __syncthreads();
    for (int s = 64; s > 0; s >>= 1) {
        if (threadIdx.x < s) {
#pragma unroll
            for (int h = 0; h < HH; h++) red[h][threadIdx.x] += red[h][threadIdx.x + s];
        }
        __syncthreads();
    }
    if (threadIdx.x < HH) {
        float v = red[threadIdx.x][0];
        g_tbl[r * HH + threadIdx.x] = 16.f / (1.f + __expf(-v));
    }
}

// ---------------- 2. bias gather ----------------
__global__ void gather_kernel(const int* __restrict__ rel_index) {
    int ij = blockIdx.x * 256 + threadIdx.x;
    int id = rel_index[ij];
#pragma unroll
    for (int h = 0; h < HH; h++)
        g_bias[h * (NT * NT) + ij] = g_tbl[id * HH + h];
}

// ---------------- expansion kernels ----------------
__global__ void expand_a_kernel(const float* __restrict__ src) {  // x -> g_xE [hi|hi|lo]
    int i = blockIdx.x * 256 + threadIdx.x;
    float a = src[i];
    __nv_bfloat16 hi = __float2bfloat16(a);
    __nv_bfloat16 lo = __float2bfloat16(a - __bfloat162float(hi));
    int m = i / CC, k = i - m * CC;
    size_t o = (size_t)m * KE + k;
    g_xE[o] = hi; g_xE[o + CC] = hi; g_xE[o + 2 * CC] = lo;
}
template <int WHICH>  // 0: qkv_w -> g_wqkvE, 1: proj_w -> g_wprojE   [hi|lo|hi]
__global__ void expand_b_kernel(const float* __restrict__ src) {
    int i = blockIdx.x * 256 + threadIdx.x;
    float a = src[i];
    __nv_bfloat16 hi = __float2bfloat16(a);
    __nv_bfloat16 lo = __float2bfloat16(a - __bfloat162float(hi));
    int n = i / CC, k = i - n * CC;
    size_t o = (size_t)n * KE + k;
    __nv_bfloat16* dst = (WHICH == 0) ? g_wqkvE : g_wprojE;
    dst[o] = hi; dst[o + CC] = lo; dst[o + 2 * CC] = hi;
}

// ---------------- mma.sync GEMM: block 128(M) x 64(N), K'=576 ----------------
// MODE 0: A=g_xE, B=g_wqkvE (576 rows). Epilogue: bias + q/k norm + scatter to g_q/g_k/g_v.
// MODE 1: A=g_attE, B=g_wprojE (192 rows). Epilogue: proj bias -> Cout.
template <int MODE>
__global__ void __launch_bounds__(256) mma_gemm(const float* __restrict__ bq,
                                                const float* __restrict__ bv,
                                                const float* __restrict__ lsc,
                                                float* __restrict__ Cout) {
    __shared__ __align__(128) unsigned char sA[128 * 128];  // 128 rows x 64 bf16
    __shared__ __align__(128) unsigned char sB[64 * 128];   // 64 rows x 64 bf16

    const int tid = threadIdx.x;
    const int wid = tid >> 5, lane = tid & 31;
    const int wm = wid >> 1, wn = wid & 1;     // warp tile: rows wm*32, cols wn*32
    const int m0 = blockIdx.y * 128;
    const int n0 = blockIdx.x * 64;

    const __nv_bfloat16* AE = (MODE == 0) ? g_xE : g_attE;
    const __nv_bfloat16* BE = (MODE == 0) ? g_wqkvE : g_wprojE;

    float acc[2][4][4];
#pragma unroll
    for (int t = 0; t < 2; t++)
#pragma unroll
        for (int nt = 0; nt < 4; nt++)
#pragma unroll
            for (int j = 0; j < 4; j++) acc[t][nt][j] = 0.f;

    // ldmatrix lane addressing
    const int li = lane & 7, lg = lane >> 3;
    const uint32_t sAu = s2u(sA), sBu = s2u(sB);
    // A: reg pattern: row = mbase + li + (lg&1)*8 ; chunk = 2s + (lg>>1)
    const int rowA0 = wm * 32 + li + (lg & 1) * 8;       // + t*16
    const int chA = lg >> 1;
    // B: row = nbase + li + (lg>>1)*8 ; chunk = 2s + (lg&1)
    const int rowB0 = wn * 32 + li + (lg >> 1) * 8;      // + p*16
    const int chB = lg & 1;

    // global-load indexing
    const int grow = tid >> 3, gseg = tid & 7;   // base for strided loads

    for (int c = 0; c < 9; c++) {
        __syncthreads();
        // A chunk: 128 rows x 4 iterations (32 rows each)
#pragma unroll
        for (int it = 0; it < 4; it++) {
            int row = grow + it * 32;
            uint4 v = ((const uint4*)(AE + (size_t)(m0 + row) * KE + c * 64))[gseg];
            *(uint4*)(sA + SWZ(row * 128 + gseg * 16)) = v;
        }
        // B chunk: 64 rows x 2 iterations
#pragma unroll
        for (int it = 0; it < 2; it++) {
            int row = grow + it * 32;
            uint4 v = ((const uint4*)(BE + (size_t)(n0 + row) * KE + c * 64))[gseg];
            *(uint4*)(sB + SWZ(row * 128 + gseg * 16)) = v;
        }
        __syncthreads();

#pragma unroll
        for (int s = 0; s < 4; s++) {
            uint32_t a[2][4], b[2][4];
#pragma unroll
            for (int t = 0; t < 2; t++) {
                int row = rowA0 + t * 16;
                uint32_t addr = sAu + row * 128 + (((2 * s + chA) ^ (row & 7)) << 4);
                ldsm4(a[t][0], a[t][1], a[t][2], a[t][3], addr);
            }
#pragma unroll
            for (int p = 0; p < 2; p++) {
                int row = rowB0 + p * 16;
                uint32_t addr = sBu + row * 128 + (((2 * s + chB) ^ (row & 7)) << 4);
                ldsm4(b[p][0], b[p][1], b[p][2], b[p][3], addr);
            }
#pragma unroll
            for (int t = 0; t < 2; t++)
#pragma unroll
                for (int nt = 0; nt < 4; nt++)
                    mma16816(acc[t][nt], a[t], &b[nt >> 1][(nt & 1) * 2]);
        }
    }

    // ---------------- epilogue ----------------
    const int nglob = n0 + wn * 32;            // warp col base (one head in MODE 0)
    const int qid = lane & 3;                  // quad position -> col pair
    if (MODE == 0) {
        const int s = nglob / 192;
        const int rem = nglob - s * 192;       // head start within 192
        const int h = rem >> 5;
        float mulq = 0.f;
        if (s == 0) mulq = __expf(fminf(lsc[h], 4.605170186f));
        float* basep = (s == 0) ? g_q : ((s == 1) ? g_k : g_v);
#pragma unroll
        for (int t = 0; t < 2; t++) {
#pragma unroll
            for (int half = 0; half < 2; half++) {
                int mrow = m0 + wm * 32 + t * 16 + half * 8 + (lane >> 2);
                float f[8];
#pragma unroll
                for (int nt = 0; nt < 4; nt++) {
                    int d0 = nt * 8 + qid * 2;
                    float b0 = (s == 0) ? bq[rem + d0] : ((s == 2) ? bv[rem + d0] : 0.f);
                    float b1 = (s == 0) ? bq[rem + d0 + 1] : ((s == 2) ? bv[rem + d0 + 1] : 0.f);
                    f[nt * 2 + 0] = acc[t][nt][half * 2 + 0] + b0;
                    f[nt * 2 + 1] = acc[t][nt][half * 2 + 1] + b1;
                }
                float mul = 1.f;
                if (s < 2) {
                    float ss = 0.f;
#pragma unroll
                    for (int j = 0; j < 8; j++) ss = fmaf(f[j], f[j], ss);
                    ss += __shfl_xor_sync(0xffffffffu, ss, 1);
                    ss += __shfl_xor_sync(0xffffffffu, ss, 2);
                    mul = 1.f / fmaxf(sqrtf(ss), 1e-12f);
                    if (s == 0) mul *= mulq;
                }
                const int bb = mrow >> 9, nr = mrow & 511;
                float* op = basep + ((((size_t)bb * HH + h) << 9) + nr) * HD;
#pragma unroll
                for (int nt = 0; nt < 4; nt++) {
                    int d0 = nt * 8 + qid * 2;
                    *(float2*)(op + d0) = make_float2(f[nt * 2] * mul, f[nt * 2 + 1] * mul);
                }
            }
        }
    } else {
#pragma unroll
        for (int t = 0; t < 2; t++) {
#pragma unroll
            for (int half = 0; half < 2; half++) {
                int mrow = m0 + wm * 32 + t * 16 + half * 8 + (lane >> 2);
                float* op = Cout + (size_t)mrow * CC + nglob;
#pragma unroll
                for (int nt = 0; nt < 4; nt++) {
                    int d0 = nt * 8 + qid * 2;
                    float pb0 = bq[nglob + d0], pb1 = bq[nglob + d0 + 1];
                    *(float2*)(op + d0) = make_float2(acc[t][nt][half * 2 + 0] + pb0,
                                                      acc[t][nt][half * 2 + 1] + pb1);
                }
            }
        }
    }
}

// ---------------- fp32 flash attention (writes expanded bf16 output) ----------------
__global__ void __launch_bounds__(128) attn_kernel(const float* __restrict__ mask) {
    const int b = blockIdx.z, h = blockIdx.y;
    const int i = blockIdx.x * 128 + threadIdx.x;
    const int w = b & (NWIN - 1);
    __shared__ float Ks[32][36];
    __shared__ float Vs[32][36];

    float4 q4[8];
    const float4* qp = (const float4*)(g_q + (((b * HH + h) << 9) + i) * HD);
#pragma unroll
    for (int u = 0; u < 8; u++) q4[u] = qp[u];

    const float4* brow = (const float4*)(g_bias + (h << 18) + (i << 9));
    const float4* mrow = (const float4*)(mask + (w << 18) + (i << 9));

    float o[32];
#pragma unroll
    for (int d = 0; d < 32; d++) o[d] = 0.f;
    float mx = -1e30f, l = 0.f;

    const int t = threadIdx.x;
    const int jr = t >> 2, qd = t & 3;
    const float* kbase = g_k + ((b * HH + h) << 9) * HD;
    const float* vbase = g_v + ((b * HH + h) << 9) * HD;

    for (int jt = 0; jt < 16; jt++) {
        __syncthreads();
        const float4* kp = (const float4*)(kbase + (jt * 32 + jr) * HD);
        const float4* vp = (const float4*)(vbase + (jt * 32 + jr) * HD);
        ((float4*)Ks[jr])[qd]     = kp[qd];
        ((float4*)Ks[jr])[qd + 4] = kp[qd + 4];
        ((float4*)Vs[jr])[qd]     = vp[qd];
        ((float4*)Vs[jr])[qd + 4] = vp[qd + 4];
        __syncthreads();

#pragma unroll
        for (int c = 0; c < 4; c++) {
            float s[8];
#pragma unroll
            for (int jj = 0; jj < 8; jj++) {
                const float4* kr = (const float4*)Ks[c * 8 + jj];
                float a = 0.f;
#pragma unroll
                for (int u = 0; u < 8; u++) {
                    float4 kv = kr[u];
                    a = fmaf(q4[u].x, kv.x, a);
                    a = fmaf(q4[u].y, kv.y, a);
                    a = fmaf(q4[u].z, kv.z, a);
                    a = fmaf(q4[u].w, kv.w, a);
                }
                s[jj] = a;
            }
            float4 b0 = brow[jt * 8 + c * 2], b1 = brow[jt * 8 + c * 2 + 1];
            float4 m0 = mrow[jt * 8 + c * 2], m1 = mrow[jt * 8 + c * 2 + 1];
            s[0] += b0.x + m0.x; s[1] += b0.y + m0.y; s[2] += b0.z + m0.z; s[3] += b0.w + m0.w;
            s[4] += b1.x + m1.x; s[5] += b1.y + m1.y; s[6] += b1.z + m1.z; s[7] += b1.w + m1.w;

            float cm = s[0];
#pragma unroll
            for (int jj = 1; jj < 8; jj++) cm = fmaxf(cm, s[jj]);
            float mnew = fmaxf(mx, cm);
            float corr = __expf(mx - mnew);
            mx = mnew;
            l *= corr;
#pragma unroll
            for (int d = 0; d < 32; d++) o[d] *= corr;
#pragma unroll
            for (int jj = 0; jj < 8; jj++) {
                float p = __expf(s[jj] - mnew);
                l += p;
                const float4* vr = (const float4*)Vs[c * 8 + jj];
#pragma unroll
                for (int u = 0; u < 8; u++) {
                    float4 vv = vr[u];
                    o[u * 4 + 0] = fmaf(p, vv.x, o[u * 4 + 0]);
                    o[u * 4 + 1] = fmaf(p, vv.y, o[u * 4 + 1]);
                    o[u * 4 + 2] = fmaf(p, vv.z, o[u * 4 + 2]);
                    o[u * 4 + 3] = fmaf(p, vv.w, o[u * 4 + 3]);
                }
            }
        }
    }

    float inv = 1.0f / l;
    unsigned short hs[32], ls[32];
#pragma unroll
    for (int j = 0; j < 32; j++) {
        float val = o[j] * inv;
        __nv_bfloat16 h16 = __float2bfloat16(val);
        __nv_bfloat16 l16 = __float2bfloat16(val - __bfloat162float(h16));
        hs[j] = *(unsigned short*)&h16;
        ls[j] = *(unsigned short*)&l16;
    }
    __nv_bfloat16* base = g_attE + (size_t)(b * NT + i) * KE + h * HD;
    uint4* p0 = (uint4*)base;
    uint4* p1 = (uint4*)(base + CC);
    uint4* p2 = (uint4*)(base + 2 * CC);
#pragma unroll
    for (int u = 0; u < 4; u++) {
        uint4 v = ((uint4*)hs)[u];
        p0[u] = v; p1[u] = v;
        p2[u] = ((uint4*)ls)[u];
    }
}

// ---------------- launch ----------------
extern "C" void kernel_launch(void* const* d_in, const int* in_sizes, int n_in,
                              void* d_out, int out_size) {
    const float* x           = (const float*)d_in[0];
    const float* mask        = (const float*)d_in[1];
    const float* qkv_w       = (const float*)d_in[2];
    const float* q_bias      = (const float*)d_in[3];
    const float* v_bias      = (const float*)d_in[4];
    const float* logit_scale = (const float*)d_in[5];
    const float* cpb_w1      = (const float*)d_in[6];
    const float* cpb_b1      = (const float*)d_in[7];
    const float* cpb_w2      = (const float*)d_in[8];
    const float* proj_w      = (const float*)d_in[9];
    const float* proj_b      = (const float*)d_in[10];
    const float* rel_table   = (const float*)d_in[11];
    const int*   rel_index   = (const int*)d_in[12];
    float* out = (float*)d_out;

    cpb_kernel<<<TBL, 128>>>(rel_table, cpb_w1, cpb_b1, cpb_w2);
    gather_kernel<<<(NT * NT) / 256, 256>>>(rel_index);
    expand_a_kernel<<<(BW * NT * CC) / 256, 256>>>(x);
    expand_b_kernel<0><<<(3 * CC * CC) / 256, 256>>>(qkv_w);
    expand_b_kernel<1><<<(CC * CC) / 256, 256>>>(proj_w);
    // QKV GEMM: N=576 -> 9 n-blocks, M=32768 -> 256 m-blocks
    mma_gemm<0><<<dim3(9, 256), 256>>>(q_bias, v_bias, logit_scale, nullptr);
    attn_kernel<<<dim3(4, HH, BW), 128>>>(mask);
    // proj GEMM: N=192 -> 3 n-blocks
    mma_gemm<1><<<dim3(3, 256), 256>>>(proj_b, nullptr, nullptr, out);
}

// round 4
// speedup vs baseline: 1.9223x; 1.7036x over previous
#include <cuda_runtime.h>
#include <cuda_bf16.h>
#include <cstdint>

// ---------------- problem constants ----------------
#define BW   64
#define NT   512
#define CC   192
#define HH   6
#define HD   32
#define NWIN 16
#define TBL  3375
#define KE   576           // expanded K = 3*192

// ---------------- device scratch ----------------
__device__ float g_tbl[TBL * HH];
__device__ float g_bias[HH * NT * NT];
__device__ float g_q[BW * HH * NT * HD];
__device__ float g_k[BW * HH * NT * HD];
__device__ float g_v[BW * HH * NT * HD];
__device__ __nv_bfloat16 g_xE[(size_t)BW * NT * KE];     // x expanded [hi|hi|lo]
__device__ __nv_bfloat16 g_attE[(size_t)BW * NT * KE];   // attn out expanded [hi|hi|lo]
__device__ __nv_bfloat16 g_wqkvE[3 * CC * KE];           // qkv_w expanded [hi|lo|hi]
__device__ __nv_bfloat16 g_wprojE[CC * KE];              // proj_w expanded [hi|lo|hi]

#define SWZ(o) ((o) ^ (((o) >> 3) & 0x70))

__device__ __forceinline__ uint32_t s2u(const void* p) {
    return (uint32_t)__cvta_generic_to_shared(p);
}
__device__ __forceinline__ void ldsm4(uint32_t& r0, uint32_t& r1, uint32_t& r2, uint32_t& r3,
                                      uint32_t addr) {
    asm volatile("ldmatrix.sync.aligned.m8n8.x4.shared.b16 {%0,%1,%2,%3}, [%4];"
                 : "=r"(r0), "=r"(r1), "=r"(r2), "=r"(r3) : "r"(addr));
}
__device__ __forceinline__ void ldsm4t(uint32_t& r0, uint32_t& r1, uint32_t& r2, uint32_t& r3,
                                       uint32_t addr) {
    asm volatile("ldmatrix.sync.aligned.m8n8.x4.trans.shared.b16 {%0,%1,%2,%3}, [%4];"
                 : "=r"(r0), "=r"(r1), "=r"(r2), "=r"(r3) : "r"(addr));
}
__device__ __forceinline__ void mma16816(float* c, const uint32_t* a, const uint32_t* b) {
    asm volatile(
        "mma.sync.aligned.m16n8k16.row.col.f32.bf16.bf16.f32 "
        "{%0,%1,%2,%3},{%4,%5,%6,%7},{%8,%9},{%0,%1,%2,%3};"
        : "+f"(c[0]), "+f"(c[1]), "+f"(c[2]), "+f"(c[3])
        : "r"(a[0]), "r"(a[1]), "r"(a[2]), "r"(a[3]), "r"(b[0]), "r"(b[1]));
}
__device__ __forceinline__ uint32_t bpack(float x, float y) {
    __nv_bfloat162 t = __floats2bfloat162_rn(x, y);
    return *(uint32_t*)&t;
}
__device__ __forceinline__ uint32_t bpack_lo(float x, float y, uint32_t hi) {
    __nv_bfloat162 h = *(__nv_bfloat162*)&hi;
    return bpack(x - __bfloat162float(h.x), y - __bfloat162float(h.y));
}
__device__ __forceinline__ void cvt_store(float4 f, unsigned char* base, int key, int qq) {
    uint32_t h0 = bpack(f.x, f.y), h1 = bpack(f.z, f.w);
    uint32_t l0 = bpack_lo(f.x, f.y, h0), l1 = bpack_lo(f.z, f.w, h1);
    *(uint2*)(base + key * 144 + qq * 8)      = make_uint2(h0, h1);
    *(uint2*)(base + key * 144 + 64 + qq * 8) = make_uint2(l0, l1);
}

// ---------------- 1. CPB MLP ----------------
__global__ void cpb_kernel(const float* __restrict__ tb, const float* __restrict__ w1,
                           const float* __restrict__ b1, const float* __restrict__ w2) {
    int r = blockIdx.x;
    float c0 = tb[r * 3 + 0], c1 = tb[r * 3 + 1], c2 = tb[r * 3 + 2];
    float acc[HH] = {0.f, 0.f, 0.f, 0.f, 0.f, 0.f};
    for (int j = threadIdx.x; j < 512; j += 128) {
        float hv = fmaf(c0, w1[j * 3 + 0], fmaf(c1, w1[j * 3 + 1], fmaf(c2, w1[j * 3 + 2], b1[j])));
        hv = fmaxf(hv, 0.f);
#pragma unroll
        for (int h = 0; h < HH; h++) acc[h] = fmaf(hv, w2[h * 512 + j], acc[h]);
    }
    __shared__ float red[HH][128];
#pragma unroll
    for (int h = 0; h < HH; h++) red[h][threadIdx.x] = acc[h];
    __syncthreads();
    for (int s = 64; s > 0; s >>= 1) {
        if (threadIdx.x < s) {
#pragma unroll
            for (int h = 0; h < HH; h++) red[h][threadIdx.x] += red[h][threadIdx.x + s];
        }
        __syncthreads();
    }
    if (threadIdx.x < HH) {
        float v = red[threadIdx.x][0];
        g_tbl[r * HH + threadIdx.x] = 16.f / (1.f + __expf(-v));
    }
}

// ---------------- 2. bias gather ----------------
__global__ void gather_kernel(const int* __restrict__ rel_index) {
    int ij = blockIdx.x * 256 + threadIdx.x;
    int id = rel_index[ij];
#pragma unroll
    for (int h = 0; h < HH; h++)
        g_bias[h * (NT * NT) + ij] = g_tbl[id * HH + h];
}

// ---------------- expansion kernels ----------------
__global__ void expand_a_kernel(const float* __restrict__ src) {  // x -> g_xE [hi|hi|lo]
    int i = blockIdx.x * 256 + threadIdx.x;
    float a = src[i];
    __nv_bfloat16 hi = __float2bfloat16(a);
    __nv_bfloat16 lo = __float2bfloat16(a - __bfloat162float(hi));
    int m = i / CC, k = i - m * CC;
    size_t o = (size_t)m * KE + k;
    g_xE[o] = hi; g_xE[o + CC] = hi; g_xE[o + 2 * CC] = lo;
}
template <int WHICH>
__global__ void expand_b_kernel(const float* __restrict__ src) {
    int i = blockIdx.x * 256 + threadIdx.x;
    float a = src[i];
    __nv_bfloat16 hi = __float2bfloat16(a);
    __nv_bfloat16 lo = __float2bfloat16(a - __bfloat162float(hi));
    int n = i / CC, k = i - n * CC;
    size_t o = (size_t)n * KE + k;
    __nv_bfloat16* dst = (WHICH == 0) ? g_wqkvE : g_wprojE;
    dst[o] = hi; dst[o + CC] = lo; dst[o + 2 * CC] = hi;
}

// ---------------- mma.sync GEMM: block 128(M) x 64(N), K'=576 ----------------
template <int MODE>
__global__ void __launch_bounds__(256) mma_gemm(const float* __restrict__ bq,
                                                const float* __restrict__ bv,
                                                const float* __restrict__ lsc,
                                                float* __restrict__ Cout) {
    __shared__ __align__(128) unsigned char sA[128 * 128];
    __shared__ __align__(128) unsigned char sB[64 * 128];

    const int tid = threadIdx.x;
    const int wid = tid >> 5, lane = tid & 31;
    const int wm = wid >> 1, wn = wid & 1;
    const int m0 = blockIdx.y * 128;
    const int n0 = blockIdx.x * 64;

    const __nv_bfloat16* AE = (MODE == 0) ? g_xE : g_attE;
    const __nv_bfloat16* BE = (MODE == 0) ? g_wqkvE : g_wprojE;

    float acc[2][4][4];
#pragma unroll
    for (int t = 0; t < 2; t++)
#pragma unroll
        for (int nt = 0; nt < 4; nt++)
#pragma unroll
            for (int j = 0; j < 4; j++) acc[t][nt][j] = 0.f;

    const int li = lane & 7, lg = lane >> 3;
    const uint32_t sAu = s2u(sA), sBu = s2u(sB);
    const int rowA0 = wm * 32 + li + (lg & 1) * 8;
    const int chA = lg >> 1;
    const int rowB0 = wn * 32 + li + (lg >> 1) * 8;
    const int chB = lg & 1;

    const int grow = tid >> 3, gseg = tid & 7;

    for (int c = 0; c < 9; c++) {
        __syncthreads();
#pragma unroll
        for (int it = 0; it < 4; it++) {
            int row = grow + it * 32;
            uint4 v = ((const uint4*)(AE + (size_t)(m0 + row) * KE + c * 64))[gseg];
            *(uint4*)(sA + SWZ(row * 128 + gseg * 16)) = v;
        }
#pragma unroll
        for (int it = 0; it < 2; it++) {
            int row = grow + it * 32;
            uint4 v = ((const uint4*)(BE + (size_t)(n0 + row) * KE + c * 64))[gseg];
            *(uint4*)(sB + SWZ(row * 128 + gseg * 16)) = v;
        }
        __syncthreads();

#pragma unroll
        for (int s = 0; s < 4; s++) {
            uint32_t a[2][4], b[2][4];
#pragma unroll
            for (int t = 0; t < 2; t++) {
                int row = rowA0 + t * 16;
                uint32_t addr = sAu + row * 128 + (((2 * s + chA) ^ (row & 7)) << 4);
                ldsm4(a[t][0], a[t][1], a[t][2], a[t][3], addr);
            }
#pragma unroll
            for (int p = 0; p < 2; p++) {
                int row = rowB0 + p * 16;
                uint32_t addr = sBu + row * 128 + (((2 * s + chB) ^ (row & 7)) << 4);
                ldsm4(b[p][0], b[p][1], b[p][2], b[p][3], addr);
            }
#pragma unroll
            for (int t = 0; t < 2; t++)
#pragma unroll
                for (int nt = 0; nt < 4; nt++)
                    mma16816(acc[t][nt], a[t], &b[nt >> 1][(nt & 1) * 2]);
        }
    }

    const int nglob = n0 + wn * 32;
    const int qid = lane & 3;
    if (MODE == 0) {
        const int s = nglob / 192;
        const int rem = nglob - s * 192;
        const int h = rem >> 5;
        float mulq = 0.f;
        if (s == 0) mulq = __expf(fminf(lsc[h], 4.605170186f));
        float* basep = (s == 0) ? g_q : ((s == 1) ? g_k : g_v);
#pragma unroll
        for (int t = 0; t < 2; t++) {
#pragma unroll
            for (int half = 0; half < 2; half++) {
                int mrow = m0 + wm * 32 + t * 16 + half * 8 + (lane >> 2);
                float f[8];
#pragma unroll
                for (int nt = 0; nt < 4; nt++) {
                    int d0 = nt * 8 + qid * 2;
                    float b0 = (s == 0) ? bq[rem + d0] : ((s == 2) ? bv[rem + d0] : 0.f);
                    float b1 = (s == 0) ? bq[rem + d0 + 1] : ((s == 2) ? bv[rem + d0 + 1] : 0.f);
                    f[nt * 2 + 0] = acc[t][nt][half * 2 + 0] + b0;
                    f[nt * 2 + 1] = acc[t][nt][half * 2 + 1] + b1;
                }
                float mul = 1.f;
                if (s < 2) {
                    float ss = 0.f;
#pragma unroll
                    for (int j = 0; j < 8; j++) ss = fmaf(f[j], f[j], ss);
                    ss += __shfl_xor_sync(0xffffffffu, ss, 1);
                    ss += __shfl_xor_sync(0xffffffffu, ss, 2);
                    mul = 1.f / fmaxf(sqrtf(ss), 1e-12f);
                    if (s == 0) mul *= mulq;
                }
                const int bb = mrow >> 9, nr = mrow & 511;
                float* op = basep + ((((size_t)bb * HH + h) << 9) + nr) * HD;
#pragma unroll
                for (int nt = 0; nt < 4; nt++) {
                    int d0 = nt * 8 + qid * 2;
                    *(float2*)(op + d0) = make_float2(f[nt * 2] * mul, f[nt * 2 + 1] * mul);
                }
            }
        }
    } else {
#pragma unroll
        for (int t = 0; t < 2; t++) {
#pragma unroll
            for (int half = 0; half < 2; half++) {
                int mrow = m0 + wm * 32 + t * 16 + half * 8 + (lane >> 2);
                float* op = Cout + (size_t)mrow * CC + nglob;
#pragma unroll
                for (int nt = 0; nt < 4; nt++) {
                    int d0 = nt * 8 + qid * 2;
                    float pb0 = bq[nglob + d0], pb1 = bq[nglob + d0 + 1];
                    *(float2*)(op + d0) = make_float2(acc[t][nt][half * 2 + 0] + pb0,
                                                      acc[t][nt][half * 2 + 1] + pb1);
                }
            }
        }
    }
}

// ---------------- tensor-core flash attention ----------------
// CTA: 128 q rows of one (b,h); 8 warps x 16 rows. K/V tiles of 64 keys.
// Panels in smem (stride 144B): K row = [khi(64B) | klo(64B)]; V row = [vhi | vlo].
__global__ void __launch_bounds__(256) attn_mma(const float* __restrict__ mask) {
    const int b = blockIdx.z, h = blockIdx.y;
    const int i0 = blockIdx.x * 128;
    const int w = b & (NWIN - 1);
    const int tid = threadIdx.x, wid = tid >> 5, lane = tid & 31;
    const int qd = lane & 3, r = lane >> 2;

    __shared__ __align__(16) unsigned char sK[64 * 144];
    __shared__ __align__(16) unsigned char sV[64 * 144];
    const uint32_t sKu = s2u(sK), sVu = s2u(sV);

    // ---- Q fragments (hi/lo) from fp32 g_q ----
    const int rowg = i0 + wid * 16 + r;
    const float* qrowA = g_q + (((size_t)(b * HH + h) << 9) + rowg) * HD;
    const float* qrowB = qrowA + 8 * HD;
    uint32_t Ahi[2][4], Alo[2][4];
#pragma unroll
    for (int c = 0; c < 2; c++) {
        float2 fa0 = *(const float2*)(qrowA + 2 * qd + 16 * c);
        float2 fb0 = *(const float2*)(qrowB + 2 * qd + 16 * c);
        float2 fa1 = *(const float2*)(qrowA + 2 * qd + 16 * c + 8);
        float2 fb1 = *(const float2*)(qrowB + 2 * qd + 16 * c + 8);
        Ahi[c][0] = bpack(fa0.x, fa0.y); Alo[c][0] = bpack_lo(fa0.x, fa0.y, Ahi[c][0]);
        Ahi[c][1] = bpack(fb0.x, fb0.y); Alo[c][1] = bpack_lo(fb0.x, fb0.y, Ahi[c][1]);
        Ahi[c][2] = bpack(fa1.x, fa1.y); Alo[c][2] = bpack_lo(fa1.x, fa1.y, Ahi[c][2]);
        Ahi[c][3] = bpack(fb1.x, fb1.y); Alo[c][3] = bpack_lo(fb1.x, fb1.y, Ahi[c][3]);
    }

    // ---- K/V staging ----
    const float* kg = g_k + (((size_t)(b * HH + h)) << 9) * HD;
    const float* vg = g_v + (((size_t)(b * HH + h)) << 9) * HD;
    const int key0 = tid >> 3, q0 = tid & 7;
    float4 kp0, kp1, vp0, vp1;
#define LOADKV(jt) { \
        const float* kr = kg + ((size_t)((jt) * 64 + key0)) * HD + q0 * 4; \
        const float* vr = vg + ((size_t)((jt) * 64 + key0)) * HD + q0 * 4; \
        kp0 = *(const float4*)kr; kp1 = *(const float4*)(kr + 32 * HD); \
        vp0 = *(const float4*)vr; vp1 = *(const float4*)(vr + 32 * HD); }
#define STAGEKV() { \
        cvt_store(kp0, sK, key0, q0); cvt_store(kp1, sK, key0 + 32, q0); \
        cvt_store(vp0, sV, key0, q0); cvt_store(vp1, sV, key0 + 32, q0); }

    LOADKV(0);
    STAGEKV();
    __syncthreads();

    // ldmatrix lane address components
    const int li = lane & 7, lg = lane >> 3;
    const uint32_t kbase = sKu + (((lg >> 1) * 8 + li) * 144) + (lg & 1) * 16;   // + jp*16*144 + chunk
    const uint32_t vbase = sVu + (((lg & 1) * 8 + li) * 144) + (lg >> 1) * 16;   // + c*16*144 + jd*32 (+64)

    // bias + mask row pointers (rows rowg, rowg+8)
    const float* pb = g_bias + ((size_t)(h * NT + rowg)) * NT + 2 * qd;
    const float* pm = mask + ((size_t)(w * NT + rowg)) * NT + 2 * qd;

    float O[4][4];
#pragma unroll
    for (int j = 0; j < 4; j++)
#pragma unroll
        for (int u = 0; u < 4; u++) O[j][u] = 0.f;
    float m0v = -1e30f, m1v = -1e30f, lsum0 = 0.f, lsum1 = 0.f;

    for (int jt = 0; jt < 8; jt++) {
        if (jt < 7) LOADKV(jt + 1);

        // ---- S = Qe . Ke^T over 64 keys ----
        float s[8][4];
#pragma unroll
        for (int j = 0; j < 8; j++)
#pragma unroll
            for (int u = 0; u < 4; u++) s[j][u] = 0.f;

#pragma unroll
        for (int jp = 0; jp < 4; jp++) {
            uint32_t h0[4], h1[4], l0r[4], l1r[4];
            uint32_t base = kbase + jp * 16 * 144;
            ldsm4(h0[0], h0[1], h0[2], h0[3], base + 0);
            ldsm4(h1[0], h1[1], h1[2], h1[3], base + 32);
            ldsm4(l0r[0], l0r[1], l0r[2], l0r[3], base + 64);
            ldsm4(l1r[0], l1r[1], l1r[2], l1r[3], base + 96);
            mma16816(s[2 * jp],     Ahi[0], h0 + 0);  mma16816(s[2 * jp],     Ahi[1], h1 + 0);
            mma16816(s[2 * jp],     Ahi[0], l0r + 0); mma16816(s[2 * jp],     Ahi[1], l1r + 0);
            mma16816(s[2 * jp],     Alo[0], h0 + 0);  mma16816(s[2 * jp],     Alo[1], h1 + 0);
            mma16816(s[2 * jp + 1], Ahi[0], h0 + 2);  mma16816(s[2 * jp + 1], Ahi[1], h1 + 2);
            mma16816(s[2 * jp + 1], Ahi[0], l0r + 2); mma16816(s[2 * jp + 1], Ahi[1], l1r + 2);
            mma16816(s[2 * jp + 1], Alo[0], h0 + 2);  mma16816(s[2 * jp + 1], Alo[1], h1 + 2);
        }

        // ---- bias + mask + online softmax ----
        float tm0 = -1e30f, tm1 = -1e30f;
#pragma unroll
        for (int j = 0; j < 8; j++) {
            int off = jt * 64 + j * 8;
            float2 bA = *(const float2*)(pb + off);
            float2 bB = *(const float2*)(pb + 8 * NT + off);
            float2 mA = *(const float2*)(pm + off);
            float2 mB = *(const float2*)(pm + 8 * NT + off);
            s[j][0] += bA.x + mA.x; s[j][1] += bA.y + mA.y;
            s[j][2] += bB.x + mB.x; s[j][3] += bB.y + mB.y;
            tm0 = fmaxf(tm0, fmaxf(s[j][0], s[j][1]));
            tm1 = fmaxf(tm1, fmaxf(s[j][2], s[j][3]));
        }
        tm0 = fmaxf(tm0, __shfl_xor_sync(0xffffffffu, tm0, 1));
        tm0 = fmaxf(tm0, __shfl_xor_sync(0xffffffffu, tm0, 2));
        tm1 = fmaxf(tm1, __shfl_xor_sync(0xffffffffu, tm1, 1));
        tm1 = fmaxf(tm1, __shfl_xor_sync(0xffffffffu, tm1, 2));
        float mn0 = fmaxf(m0v, tm0), mn1 = fmaxf(m1v, tm1);
        float c0 = __expf(m0v - mn0), c1 = __expf(m1v - mn1);
        m0v = mn0; m1v = mn1;
        lsum0 *= c0; lsum1 *= c1;
#pragma unroll
        for (int j = 0; j < 4; j++) {
            O[j][0] *= c0; O[j][1] *= c0; O[j][2] *= c1; O[j][3] *= c1;
        }
#pragma unroll
        for (int j = 0; j < 8; j++) {
            s[j][0] = __expf(s[j][0] - mn0); s[j][1] = __expf(s[j][1] - mn0);
            s[j][2] = __expf(s[j][2] - mn1); s[j][3] = __expf(s[j][3] - mn1);
            lsum0 += s[j][0] + s[j][1];
            lsum1 += s[j][2] + s[j][3];
        }

        // ---- P fragments (hi/lo) ----
        uint32_t Phi[4][4], Plo[4][4];
#pragma unroll
        for (int c = 0; c < 4; c++) {
            Phi[c][0] = bpack(s[2 * c][0], s[2 * c][1]);
            Plo[c][0] = bpack_lo(s[2 * c][0], s[2 * c][1], Phi[c][0]);
            Phi[c][1] = bpack(s[2 * c][2], s[2 * c][3]);
            Plo[c][1] = bpack_lo(s[2 * c][2], s[2 * c][3], Phi[c][1]);
            Phi[c][2] = bpack(s[2 * c + 1][0], s[2 * c + 1][1]);
            Plo[c][2] = bpack_lo(s[2 * c + 1][0], s[2 * c + 1][1], Phi[c][2]);
            Phi[c][3] = bpack(s[2 * c + 1][2], s[2 * c + 1][3]);
            Plo[c][3] = bpack_lo(s[2 * c + 1][2], s[2 * c + 1][3], Phi[c][3]);
        }

        // ---- O += P . V  (3-product) ----
#pragma unroll
        for (int c = 0; c < 4; c++) {
#pragma unroll
            for (int jd = 0; jd < 2; jd++) {
                uint32_t vh[4], vl[4];
                uint32_t base = vbase + c * 16 * 144 + jd * 32;
                ldsm4t(vh[0], vh[1], vh[2], vh[3], base);
                ldsm4t(vl[0], vl[1], vl[2], vl[3], base + 64);
                mma16816(O[2 * jd],     Phi[c], vh + 0);
                mma16816(O[2 * jd],     Plo[c], vh + 0);
                mma16816(O[2 * jd],     Phi[c], vl + 0);
                mma16816(O[2 * jd + 1], Phi[c], vh + 2);
                mma16816(O[2 * jd + 1], Plo[c], vh + 2);
                mma16816(O[2 * jd + 1], Phi[c], vl + 2);
            }
        }

        __syncthreads();
        if (jt < 7) {
            STAGEKV();
            __syncthreads();
        }
    }

    // ---- epilogue ----
    lsum0 += __shfl_xor_sync(0xffffffffu, lsum0, 1);
    lsum0 += __shfl_xor_sync(0xffffffffu, lsum0, 2);
    lsum1 += __shfl_xor_sync(0xffffffffu, lsum1, 1);
    lsum1 += __shfl_xor_sync(0xffffffffu, lsum1, 2);
    float inv0 = 1.f / lsum0, inv1 = 1.f / lsum1;

    __nv_bfloat16* baseA = g_attE + (size_t)(b * NT + rowg) * KE + h * HD + 2 * qd;
    __nv_bfloat16* baseB = baseA + (size_t)8 * KE;
#pragma unroll
    for (int j = 0; j < 4; j++) {
        int col = j * 8;
        uint32_t hiA = bpack(O[j][0] * inv0, O[j][1] * inv0);
        uint32_t loA = bpack_lo(O[j][0] * inv0, O[j][1] * inv0, hiA);
        *(uint32_t*)(baseA + col)       = hiA;
        *(uint32_t*)(baseA + col + CC)  = hiA;
        *(uint32_t*)(baseA + col + 2 * CC) = loA;
        uint32_t hiB = bpack(O[j][2] * inv1, O[j][3] * inv1);
        uint32_t loB = bpack_lo(O[j][2] * inv1, O[j][3] * inv1, hiB);
        *(uint32_t*)(baseB + col)       = hiB;
        *(uint32_t*)(baseB + col + CC)  = hiB;
        *(uint32_t*)(baseB + col + 2 * CC) = loB;
    }
#undef LOADKV
#undef STAGEKV
}

// ---------------- launch ----------------
extern "C" void kernel_launch(void* const* d_in, const int* in_sizes, int n_in,
                              void* d_out, int out_size) {
    const float* x           = (const float*)d_in[0];
    const float* mask        = (const float*)d_in[1];
    const float* qkv_w       = (const float*)d_in[2];
    const float* q_bias      = (const float*)d_in[3];
    const float* v_bias      = (const float*)d_in[4];
    const float* logit_scale = (const float*)d_in[5];
    const float* cpb_w1      = (const float*)d_in[6];
    const float* cpb_b1      = (const float*)d_in[7];
    const float* cpb_w2      = (const float*)d_in[8];
    const float* proj_w      = (const float*)d_in[9];
    const float* proj_b      = (const float*)d_in[10];
    const float* rel_table   = (const float*)d_in[11];
    const int*   rel_index   = (const int*)d_in[12];
    float* out = (float*)d_out;

    cpb_kernel<<<TBL, 128>>>(rel_table, cpb_w1, cpb_b1, cpb_w2);
    gather_kernel<<<(NT * NT) / 256, 256>>>(rel_index);
    expand_a_kernel<<<(BW * NT * CC) / 256, 256>>>(x);
    expand_b_kernel<0><<<(3 * CC * CC) / 256, 256>>>(qkv_w);
    expand_b_kernel<1><<<(CC * CC) / 256, 256>>>(proj_w);
    mma_gemm<0><<<dim3(9, 256), 256>>>(q_bias, v_bias, logit_scale, nullptr);
    attn_mma<<<dim3(4, HH, BW), 256>>>(mask);
    mma_gemm<1><<<dim3(3, 256), 256>>>(proj_b, nullptr, nullptr, out);
}

// round 5
// speedup vs baseline: 2.1921x; 1.1404x over previous
#include <cuda_runtime.h>
#include <cuda_bf16.h>
#include <cstdint>

// ---------------- problem constants ----------------
#define BW   64
#define NT   512
#define CC   192
#define HH   6
#define HD   32
#define NWIN 16
#define TBL  3375
#define KE   576           // expanded K = 3*192

// ---------------- device scratch ----------------
__device__ float g_tbl[TBL * HH];
__device__ float g_bias[HH * NT * NT];
__device__ float g_q[BW * HH * NT * HD];
__device__ float g_k[BW * HH * NT * HD];
__device__ float g_v[BW * HH * NT * HD];
__device__ __nv_bfloat16 g_xE[(size_t)BW * NT * KE];     // x expanded [hi|hi|lo]
__device__ __nv_bfloat16 g_attE[(size_t)BW * NT * KE];   // attn out expanded [hi|hi|lo]
__device__ __nv_bfloat16 g_wqkvE[3 * CC * KE];           // qkv_w expanded [hi|lo|hi]
__device__ __nv_bfloat16 g_wprojE[CC * KE];              // proj_w expanded [hi|lo|hi]

#define SWZ(o) ((o) ^ (((o) >> 3) & 0x70))

__device__ __forceinline__ uint32_t s2u(const void* p) {
    return (uint32_t)__cvta_generic_to_shared(p);
}
__device__ __forceinline__ void ldsm4(uint32_t& r0, uint32_t& r1, uint32_t& r2, uint32_t& r3,
                                      uint32_t addr) {
    asm volatile("ldmatrix.sync.aligned.m8n8.x4.shared.b16 {%0,%1,%2,%3}, [%4];"
                 : "=r"(r0), "=r"(r1), "=r"(r2), "=r"(r3) : "r"(addr));
}
__device__ __forceinline__ void ldsm4t(uint32_t& r0, uint32_t& r1, uint32_t& r2, uint32_t& r3,
                                       uint32_t addr) {
    asm volatile("ldmatrix.sync.aligned.m8n8.x4.trans.shared.b16 {%0,%1,%2,%3}, [%4];"
                 : "=r"(r0), "=r"(r1), "=r"(r2), "=r"(r3) : "r"(addr));
}
__device__ __forceinline__ void mma16816(float* c, const uint32_t* a, const uint32_t* b) {
    asm volatile(
        "mma.sync.aligned.m16n8k16.row.col.f32.bf16.bf16.f32 "
        "{%0,%1,%2,%3},{%4,%5,%6,%7},{%8,%9},{%0,%1,%2,%3};"
        : "+f"(c[0]), "+f"(c[1]), "+f"(c[2]), "+f"(c[3])
        : "r"(a[0]), "r"(a[1]), "r"(a[2]), "r"(a[3]), "r"(b[0]), "r"(b[1]));
}
__device__ __forceinline__ void cpasync16(uint32_t smem, const void* g) {
    asm volatile("cp.async.cg.shared.global [%0], [%1], 16;" :: "r"(smem), "l"(g));
}
#define CP_COMMIT() asm volatile("cp.async.commit_group;" ::: "memory")
#define CP_WAIT1()  asm volatile("cp.async.wait_group 1;" ::: "memory")
#define CP_WAIT0()  asm volatile("cp.async.wait_group 0;" ::: "memory")

__device__ __forceinline__ uint32_t bpack(float x, float y) {
    __nv_bfloat162 t = __floats2bfloat162_rn(x, y);
    return *(uint32_t*)&t;
}
__device__ __forceinline__ uint32_t bpack_lo(float x, float y, uint32_t hi) {
    __nv_bfloat162 h = *(__nv_bfloat162*)&hi;
    return bpack(x - __bfloat162float(h.x), y - __bfloat162float(h.y));
}
__device__ __forceinline__ void cvt_store(float4 f, unsigned char* base, int key, int qq) {
    uint32_t h0 = bpack(f.x, f.y), h1 = bpack(f.z, f.w);
    uint32_t l0 = bpack_lo(f.x, f.y, h0), l1 = bpack_lo(f.z, f.w, h1);
    *(uint2*)(base + key * 144 + qq * 8)      = make_uint2(h0, h1);
    *(uint2*)(base + key * 144 + 64 + qq * 8) = make_uint2(l0, l1);
}

// ---------------- 1. CPB MLP ----------------
__global__ void cpb_kernel(const float* __restrict__ tb, const float* __restrict__ w1,
                           const float* __restrict__ b1, const float* __restrict__ w2) {
    int r = blockIdx.x;
    float c0 = tb[r * 3 + 0], c1 = tb[r * 3 + 1], c2 = tb[r * 3 + 2];
    float acc[HH] = {0.f, 0.f, 0.f, 0.f, 0.f, 0.f};
    for (int j = threadIdx.x; j < 512; j += 128) {
        float hv = fmaf(c0, w1[j * 3 + 0], fmaf(c1, w1[j * 3 + 1], fmaf(c2, w1[j * 3 + 2], b1[j])));
        hv = fmaxf(hv, 0.f);
#pragma unroll
        for (int h = 0; h < HH; h++) acc[h] = fmaf(hv, w2[h * 512 + j], acc[h]);
    }
    __shared__ float red[HH][128];
#pragma unroll
    for (int h = 0; h < HH; h++) red[h][threadIdx.x] = acc[h];
    __syncthreads();
    for (int s = 64; s > 0; s >>= 1) {
        if (threadIdx.x < s) {
#pragma unroll
            for (int h = 0; h < HH; h++) red[h][threadIdx.x] += red[h][threadIdx.x + s];
        }
        __syncthreads();
    }
    if (threadIdx.x < HH) {
        float v = red[threadIdx.x][0];
        g_tbl[r * HH + threadIdx.x] = 16.f / (1.f + __expf(-v));
    }
}

// ---------------- 2. bias gather ----------------
__global__ void gather_kernel(const int* __restrict__ rel_index) {
    int ij = blockIdx.x * 256 + threadIdx.x;
    int id = rel_index[ij];
#pragma unroll
    for (int h = 0; h < HH; h++)
        g_bias[h * (NT * NT) + ij] = g_tbl[id * HH + h];
}

// ---------------- expansion kernels ----------------
__global__ void expand_a_kernel(const float* __restrict__ src) {  // x -> g_xE [hi|hi|lo]
    int i = blockIdx.x * 256 + threadIdx.x;
    float a = src[i];
    __nv_bfloat16 hi = __float2bfloat16(a);
    __nv_bfloat16 lo = __float2bfloat16(a - __bfloat162float(hi));
    int m = i / CC, k = i - m * CC;
    size_t o = (size_t)m * KE + k;
    g_xE[o] = hi; g_xE[o + CC] = hi; g_xE[o + 2 * CC] = lo;
}
template <int WHICH>
__global__ void expand_b_kernel(const float* __restrict__ src) {
    int i = blockIdx.x * 256 + threadIdx.x;
    float a = src[i];
    __nv_bfloat16 hi = __float2bfloat16(a);
    __nv_bfloat16 lo = __float2bfloat16(a - __bfloat162float(hi));
    int n = i / CC, k = i - n * CC;
    size_t o = (size_t)n * KE + k;
    __nv_bfloat16* dst = (WHICH == 0) ? g_wqkvE : g_wprojE;
    dst[o] = hi; dst[o + CC] = lo; dst[o + 2 * CC] = hi;
}

// ---------------- mma.sync GEMM: block 128(M) x 64(N), K'=576, cp.async 2-stage ----------------
template <int MODE>
__global__ void __launch_bounds__(256) mma_gemm(const float* __restrict__ bq,
                                                const float* __restrict__ bv,
                                                const float* __restrict__ lsc,
                                                float* __restrict__ Cout) {
    // layout: A0 @0 (16K), A1 @16384, B0 @32768 (8K), B1 @40960  -> 48KB
    __shared__ __align__(128) unsigned char smem_all[49152];

    const int tid = threadIdx.x;
    const int wid = tid >> 5, lane = tid & 31;
    const int wm = wid >> 1, wn = wid & 1;
    const int m0 = blockIdx.y * 128;
    const int n0 = blockIdx.x * 64;

    const __nv_bfloat16* AE = (MODE == 0) ? g_xE : g_attE;
    const __nv_bfloat16* BE = (MODE == 0) ? g_wqkvE : g_wprojE;

    float acc[2][4][4];
#pragma unroll
    for (int t = 0; t < 2; t++)
#pragma unroll
        for (int nt = 0; nt < 4; nt++)
#pragma unroll
            for (int j = 0; j < 4; j++) acc[t][nt][j] = 0.f;

    const int li = lane & 7, lg = lane >> 3;
    const uint32_t sAu = s2u(smem_all), sBu = s2u(smem_all + 32768);
    const int rowA0 = wm * 32 + li + (lg & 1) * 8;
    const int chA = lg >> 1;
    const int rowB0 = wn * 32 + li + (lg >> 1) * 8;
    const int chB = lg & 1;

    const int grow = tid >> 3, gseg = tid & 7;

#define GSTAGE(c, buf) { \
        uint32_t aB = sAu + (buf) * 16384; \
        uint32_t bB = sBu + (buf) * 8192;  \
        _Pragma("unroll") \
        for (int it = 0; it < 4; it++) { \
            int row = grow + it * 32; \
            cpasync16(aB + SWZ(row * 128 + gseg * 16), \
                      AE + (size_t)(m0 + row) * KE + (c) * 64 + gseg * 8); \
        } \
        _Pragma("unroll") \
        for (int it = 0; it < 2; it++) { \
            int row = grow + it * 32; \
            cpasync16(bB + SWZ(row * 128 + gseg * 16), \
                      BE + (size_t)(n0 + row) * KE + (c) * 64 + gseg * 8); \
        } \
        CP_COMMIT(); }

    GSTAGE(0, 0);

    for (int c = 0; c < 9; c++) {
        __syncthreads();   // all warps done reading buf[(c+1)&1] from iter c-1
        if (c < 8) { GSTAGE(c + 1, (c + 1) & 1); CP_WAIT1(); }
        else CP_WAIT0();
        __syncthreads();   // buf[c&1] visible

        uint32_t aB = sAu + (c & 1) * 16384;
        uint32_t bB = sBu + (c & 1) * 8192;
#pragma unroll
        for (int s = 0; s < 4; s++) {
            uint32_t a[2][4], b[2][4];
#pragma unroll
            for (int t = 0; t < 2; t++) {
                int row = rowA0 + t * 16;
                uint32_t addr = aB + row * 128 + (((2 * s + chA) ^ (row & 7)) << 4);
                ldsm4(a[t][0], a[t][1], a[t][2], a[t][3], addr);
            }
#pragma unroll
            for (int p = 0; p < 2; p++) {
                int row = rowB0 + p * 16;
                uint32_t addr = bB + row * 128 + (((2 * s + chB) ^ (row & 7)) << 4);
                ldsm4(b[p][0], b[p][1], b[p][2], b[p][3], addr);
            }
#pragma unroll
            for (int t = 0; t < 2; t++)
#pragma unroll
                for (int nt = 0; nt < 4; nt++)
                    mma16816(acc[t][nt], a[t], &b[nt >> 1][(nt & 1) * 2]);
        }
    }
#undef GSTAGE

    const int nglob = n0 + wn * 32;
    const int qid = lane & 3;
    if (MODE == 0) {
        const int s = nglob / 192;
        const int rem = nglob - s * 192;
        const int h = rem >> 5;
        float mulq = 0.f;
        if (s == 0) mulq = __expf(fminf(lsc[h], 4.605170186f));
        float* basep = (s == 0) ? g_q : ((s == 1) ? g_k : g_v);
#pragma unroll
        for (int t = 0; t < 2; t++) {
#pragma unroll
            for (int half = 0; half < 2; half++) {
                int mrow = m0 + wm * 32 + t * 16 + half * 8 + (lane >> 2);
                float f[8];
#pragma unroll
                for (int nt = 0; nt < 4; nt++) {
                    int d0 = nt * 8 + qid * 2;
                    float b0 = (s == 0) ? bq[rem + d0] : ((s == 2) ? bv[rem + d0] : 0.f);
                    float b1 = (s == 0) ? bq[rem + d0 + 1] : ((s == 2) ? bv[rem + d0 + 1] : 0.f);
                    f[nt * 2 + 0] = acc[t][nt][half * 2 + 0] + b0;
                    f[nt * 2 + 1] = acc[t][nt][half * 2 + 1] + b1;
                }
                float mul = 1.f;
                if (s < 2) {
                    float ss = 0.f;
#pragma unroll
                    for (int j = 0; j < 8; j++) ss = fmaf(f[j], f[j], ss);
                    ss += __shfl_xor_sync(0xffffffffu, ss, 1);
                    ss += __shfl_xor_sync(0xffffffffu, ss, 2);
                    mul = 1.f / fmaxf(sqrtf(ss), 1e-12f);
                    if (s == 0) mul *= mulq;
                }
                const int bb = mrow >> 9, nr = mrow & 511;
                float* op = basep + ((((size_t)bb * HH + h) << 9) + nr) * HD;
#pragma unroll
                for (int nt = 0; nt < 4; nt++) {
                    int d0 = nt * 8 + qid * 2;
                    *(float2*)(op + d0) = make_float2(f[nt * 2] * mul, f[nt * 2 + 1] * mul);
                }
            }
        }
    } else {
#pragma unroll
        for (int t = 0; t < 2; t++) {
#pragma unroll
            for (int half = 0; half < 2; half++) {
                int mrow = m0 + wm * 32 + t * 16 + half * 8 + (lane >> 2);
                float* op = Cout + (size_t)mrow * CC + nglob;
#pragma unroll
                for (int nt = 0; nt < 4; nt++) {
                    int d0 = nt * 8 + qid * 2;
                    float pb0 = bq[nglob + d0], pb1 = bq[nglob + d0 + 1];
                    *(float2*)(op + d0) = make_float2(acc[t][nt][half * 2 + 0] + pb0,
                                                      acc[t][nt][half * 2 + 1] + pb1);
                }
            }
        }
    }
}

// ---------------- tensor-core flash attention (double-buffered K/V) ----------------
__global__ void __launch_bounds__(256) attn_mma(const float* __restrict__ mask) {
    const int b = blockIdx.z, h = blockIdx.y;
    const int i0 = blockIdx.x * 128;
    const int w = b & (NWIN - 1);
    const int tid = threadIdx.x, wid = tid >> 5, lane = tid & 31;
    const int qd = lane & 3, r = lane >> 2;

    __shared__ __align__(16) unsigned char sK[2][64 * 144];
    __shared__ __align__(16) unsigned char sV[2][64 * 144];
    const uint32_t sKu = s2u(sK), sVu = s2u(sV);

    // ---- Q fragments (hi/lo) from fp32 g_q ----
    const int rowg = i0 + wid * 16 + r;
    const float* qrowA = g_q + (((size_t)(b * HH + h) << 9) + rowg) * HD;
    const float* qrowB = qrowA + 8 * HD;
    uint32_t Ahi[2][4], Alo[2][4];
#pragma unroll
    for (int c = 0; c < 2; c++) {
        float2 fa0 = *(const float2*)(qrowA + 2 * qd + 16 * c);
        float2 fb0 = *(const float2*)(qrowB + 2 * qd + 16 * c);
        float2 fa1 = *(const float2*)(qrowA + 2 * qd + 16 * c + 8);
        float2 fb1 = *(const float2*)(qrowB + 2 * qd + 16 * c + 8);
        Ahi[c][0] = bpack(fa0.x, fa0.y); Alo[c][0] = bpack_lo(fa0.x, fa0.y, Ahi[c][0]);
        Ahi[c][1] = bpack(fb0.x, fb0.y); Alo[c][1] = bpack_lo(fb0.x, fb0.y, Ahi[c][1]);
        Ahi[c][2] = bpack(fa1.x, fa1.y); Alo[c][2] = bpack_lo(fa1.x, fa1.y, Ahi[c][2]);
        Ahi[c][3] = bpack(fb1.x, fb1.y); Alo[c][3] = bpack_lo(fb1.x, fb1.y, Ahi[c][3]);
    }

    // ---- K/V staging ----
    const float* kg = g_k + (((size_t)(b * HH + h)) << 9) * HD;
    const float* vg = g_v + (((size_t)(b * HH + h)) << 9) * HD;
    const int key0 = tid >> 3, q0 = tid & 7;
    float4 kp0, kp1, vp0, vp1;
#define LOADKV(jt) { \
        const float* kr = kg + ((size_t)((jt) * 64 + key0)) * HD + q0 * 4; \
        const float* vr = vg + ((size_t)((jt) * 64 + key0)) * HD + q0 * 4; \
        kp0 = *(const float4*)kr; kp1 = *(const float4*)(kr + 32 * HD); \
        vp0 = *(const float4*)vr; vp1 = *(const float4*)(vr + 32 * HD); }
#define STAGEKV(buf) { \
        cvt_store(kp0, sK[buf], key0, q0); cvt_store(kp1, sK[buf], key0 + 32, q0); \
        cvt_store(vp0, sV[buf], key0, q0); cvt_store(vp1, sV[buf], key0 + 32, q0); }

    LOADKV(0);
    STAGEKV(0);
    __syncthreads();

    const int li = lane & 7, lg = lane >> 3;
    const uint32_t kbase = sKu + (((lg >> 1) * 8 + li) * 144) + (lg & 1) * 16;
    const uint32_t vbase = sVu + (((lg & 1) * 8 + li) * 144) + (lg >> 1) * 16;

    const float* pb = g_bias + ((size_t)(h * NT + rowg)) * NT + 2 * qd;
    const float* pm = mask + ((size_t)(w * NT + rowg)) * NT + 2 * qd;

    float O[4][4];
#pragma unroll
    for (int j = 0; j < 4; j++)
#pragma unroll
        for (int u = 0; u < 4; u++) O[j][u] = 0.f;
    float m0v = -1e30f, m1v = -1e30f, lsum0 = 0.f, lsum1 = 0.f;

    for (int jt = 0; jt < 8; jt++) {
        const int buf = jt & 1;
        if (jt < 7) LOADKV(jt + 1);          // gmem K/V in flight behind compute

        // ---- init S with bias + mask (LDG latency hides behind QK mmas) ----
        float s[8][4];
#pragma unroll
        for (int j = 0; j < 8; j++) {
            int off = jt * 64 + j * 8;
            float2 bA = *(const float2*)(pb + off);
            float2 bB = *(const float2*)(pb + 8 * NT + off);
            float2 mA = *(const float2*)(pm + off);
            float2 mB = *(const float2*)(pm + 8 * NT + off);
            s[j][0] = bA.x + mA.x; s[j][1] = bA.y + mA.y;
            s[j][2] = bB.x + mB.x; s[j][3] = bB.y + mB.y;
        }

        // ---- S += Qe . Ke^T over 64 keys ----
#pragma unroll
        for (int jp = 0; jp < 4; jp++) {
            uint32_t h0[4], h1[4], l0r[4], l1r[4];
            uint32_t base = kbase + buf * (64 * 144) + jp * 16 * 144;
            ldsm4(h0[0], h0[1], h0[2], h0[3], base + 0);
            ldsm4(h1[0], h1[1], h1[2], h1[3], base + 32);
            ldsm4(l0r[0], l0r[1], l0r[2], l0r[3], base + 64);
            ldsm4(l1r[0], l1r[1], l1r[2], l1r[3], base + 96);
            mma16816(s[2 * jp],     Ahi[0], h0 + 0);  mma16816(s[2 * jp],     Ahi[1], h1 + 0);
            mma16816(s[2 * jp],     Ahi[0], l0r + 0); mma16816(s[2 * jp],     Ahi[1], l1r + 0);
            mma16816(s[2 * jp],     Alo[0], h0 + 0);  mma16816(s[2 * jp],     Alo[1], h1 + 0);
            mma16816(s[2 * jp + 1], Ahi[0], h0 + 2);  mma16816(s[2 * jp + 1], Ahi[1], h1 + 2);
            mma16816(s[2 * jp + 1], Ahi[0], l0r + 2); mma16816(s[2 * jp + 1], Ahi[1], l1r + 2);
            mma16816(s[2 * jp + 1], Alo[0], h0 + 2);  mma16816(s[2 * jp + 1], Alo[1], h1 + 2);
        }

        // ---- online softmax ----
        float tm0 = -1e30f, tm1 = -1e30f;
#pragma unroll
        for (int j = 0; j < 8; j++) {
            tm0 = fmaxf(tm0, fmaxf(s[j][0], s[j][1]));
            tm1 = fmaxf(tm1, fmaxf(s[j][2], s[j][3]));
        }
        tm0 = fmaxf(tm0, __shfl_xor_sync(0xffffffffu, tm0, 1));
        tm0 = fmaxf(tm0, __shfl_xor_sync(0xffffffffu, tm0, 2));
        tm1 = fmaxf(tm1, __shfl_xor_sync(0xffffffffu, tm1, 1));
        tm1 = fmaxf(tm1, __shfl_xor_sync(0xffffffffu, tm1, 2));
        float mn0 = fmaxf(m0v, tm0), mn1 = fmaxf(m1v, tm1);
        float c0 = __expf(m0v - mn0), c1 = __expf(m1v - mn1);
        m0v = mn0; m1v = mn1;
        lsum0 *= c0; lsum1 *= c1;
#pragma unroll
        for (int j = 0; j < 4; j++) {
            O[j][0] *= c0; O[j][1] *= c0; O[j][2] *= c1; O[j][3] *= c1;
        }
#pragma unroll
        for (int j = 0; j < 8; j++) {
            s[j][0] = __expf(s[j][0] - mn0); s[j][1] = __expf(s[j][1] - mn0);
            s[j][2] = __expf(s[j][2] - mn1); s[j][3] = __expf(s[j][3] - mn1);
            lsum0 += s[j][0] + s[j][1];
            lsum1 += s[j][2] + s[j][3];
        }

        // ---- P fragments (hi/lo) ----
        uint32_t Phi[4][4], Plo[4][4];
#pragma unroll
        for (int c = 0; c < 4; c++) {
            Phi[c][0] = bpack(s[2 * c][0], s[2 * c][1]);
            Plo[c][0] = bpack_lo(s[2 * c][0], s[2 * c][1], Phi[c][0]);
            Phi[c][1] = bpack(s[2 * c][2], s[2 * c][3]);
            Plo[c][1] = bpack_lo(s[2 * c][2], s[2 * c][3], Phi[c][1]);
            Phi[c][2] = bpack(s[2 * c + 1][0], s[2 * c + 1][1]);
            Plo[c][2] = bpack_lo(s[2 * c + 1][0], s[2 * c + 1][1], Phi[c][2]);
            Phi[c][3] = bpack(s[2 * c + 1][2], s[2 * c + 1][3]);
            Plo[c][3] = bpack_lo(s[2 * c + 1][2], s[2 * c + 1][3], Phi[c][3]);
        }

        // ---- O += P . V  (3-product) ----
#pragma unroll
        for (int c = 0; c < 4; c++) {
#pragma unroll
            for (int jd = 0; jd < 2; jd++) {
                uint32_t vh[4], vl[4];
                uint32_t base = vbase + buf * (64 * 144) + c * 16 * 144 + jd * 32;
                ldsm4t(vh[0], vh[1], vh[2], vh[3], base);
                ldsm4t(vl[0], vl[1], vl[2], vl[3], base + 64);
                mma16816(O[2 * jd],     Phi[c], vh + 0);
                mma16816(O[2 * jd],     Plo[c], vh + 0);
                mma16816(O[2 * jd],     Phi[c], vl + 0);
                mma16816(O[2 * jd + 1], Phi[c], vh + 2);
                mma16816(O[2 * jd + 1], Plo[c], vh + 2);
                mma16816(O[2 * jd + 1], Phi[c], vl + 2);
            }
        }

        if (jt < 7) STAGEKV(buf ^ 1);   // writes other buffer; no pre-sync needed
        __syncthreads();                // staging visible; reads of buf done before reuse
    }

    // ---- epilogue ----
    lsum0 += __shfl_xor_sync(0xffffffffu, lsum0, 1);
    lsum0 += __shfl_xor_sync(0xffffffffu, lsum0, 2);
    lsum1 += __shfl_xor_sync(0xffffffffu, lsum1, 1);
    lsum1 += __shfl_xor_sync(0xffffffffu, lsum1, 2);
    float inv0 = 1.f / lsum0, inv1 = 1.f / lsum1;

    __nv_bfloat16* baseA = g_attE + (size_t)(b * NT + rowg) * KE + h * HD + 2 * qd;
    __nv_bfloat16* baseB = baseA + (size_t)8 * KE;
#pragma unroll
    for (int j = 0; j < 4; j++) {
        int col = j * 8;
        uint32_t hiA = bpack(O[j][0] * inv0, O[j][1] * inv0);
        uint32_t loA = bpack_lo(O[j][0] * inv0, O[j][1] * inv0, hiA);
        *(uint32_t*)(baseA + col)       = hiA;
        *(uint32_t*)(baseA + col + CC)  = hiA;
        *(uint32_t*)(baseA + col + 2 * CC) = loA;
        uint32_t hiB = bpack(O[j][2] * inv1, O[j][3] * inv1);
        uint32_t loB = bpack_lo(O[j][2] * inv1, O[j][3] * inv1, hiB);
        *(uint32_t*)(baseB + col)       = hiB;
        *(uint32_t*)(baseB + col + CC)  = hiB;
        *(uint32_t*)(baseB + col + 2 * CC) = loB;
    }
#undef LOADKV
#undef STAGEKV
}

// ---------------- launch ----------------
extern "C" void kernel_launch(void* const* d_in, const int* in_sizes, int n_in,
                              void* d_out, int out_size) {
    const float* x           = (const float*)d_in[0];
    const float* mask        = (const float*)d_in[1];
    const float* qkv_w       = (const float*)d_in[2];
    const float* q_bias      = (const float*)d_in[3];
    const float* v_bias      = (const float*)d_in[4];
    const float* logit_scale = (const float*)d_in[5];
    const float* cpb_w1      = (const float*)d_in[6];
    const float* cpb_b1      = (const float*)d_in[7];
    const float* cpb_w2      = (const float*)d_in[8];
    const float* proj_w      = (const float*)d_in[9];
    const float* proj_b      = (const float*)d_in[10];
    const float* rel_table   = (const float*)d_in[11];
    const int*   rel_index   = (const int*)d_in[12];
    float* out = (float*)d_out;

    cpb_kernel<<<TBL, 128>>>(rel_table, cpb_w1, cpb_b1, cpb_w2);
    gather_kernel<<<(NT * NT) / 256, 256>>>(rel_index);
    expand_a_kernel<<<(BW * NT * CC) / 256, 256>>>(x);
    expand_b_kernel<0><<<(3 * CC * CC) / 256, 256>>>(qkv_w);
    expand_b_kernel<1><<<(CC * CC) / 256, 256>>>(proj_w);
    mma_gemm<0><<<dim3(9, 256), 256>>>(q_bias, v_bias, logit_scale, nullptr);
    attn_mma<<<dim3(4, HH, BW), 256>>>(mask);
    mma_gemm<1><<<dim3(3, 256), 256>>>(proj_b, nullptr, nullptr, out);
}

// round 6
// speedup vs baseline: 2.5587x; 1.1672x over previous
#include <cuda_runtime.h>
#include <cuda_bf16.h>
#include <cstdint>

// ---------------- problem constants ----------------
#define BW   64
#define NT   512
#define CC   192
#define HH   6
#define HD   32
#define NWIN 16
#define TBL  3375
#define KE   576           // expanded K = 3*192

// ---------------- device scratch ----------------
__device__ float g_tbl[TBL * HH];
__device__ float g_bias[HH * NT * NT];
__device__ float g_q[BW * HH * NT * HD];
// k/v stored pre-expanded: per key row = [hi 64B | lo 64B]
__device__ unsigned char g_kE[(size_t)BW * HH * NT * 128];
__device__ unsigned char g_vE[(size_t)BW * HH * NT * 128];
__device__ __nv_bfloat16 g_xE[(size_t)BW * NT * KE];     // x expanded [hi|hi|lo]
__device__ __nv_bfloat16 g_attE[(size_t)BW * NT * KE];   // attn out expanded [hi|hi|lo]
__device__ __nv_bfloat16 g_wqkvE[3 * CC * KE];           // qkv_w expanded [hi|lo|hi]
__device__ __nv_bfloat16 g_wprojE[CC * KE];              // proj_w expanded [hi|lo|hi]

#define SWZ(o) ((o) ^ (((o) >> 3) & 0x70))

__device__ __forceinline__ uint32_t s2u(const void* p) {
    return (uint32_t)__cvta_generic_to_shared(p);
}
__device__ __forceinline__ void ldsm4(uint32_t& r0, uint32_t& r1, uint32_t& r2, uint32_t& r3,
                                      uint32_t addr) {
    asm volatile("ldmatrix.sync.aligned.m8n8.x4.shared.b16 {%0,%1,%2,%3}, [%4];"
                 : "=r"(r0), "=r"(r1), "=r"(r2), "=r"(r3) : "r"(addr));
}
__device__ __forceinline__ void ldsm4t(uint32_t& r0, uint32_t& r1, uint32_t& r2, uint32_t& r3,
                                       uint32_t addr) {
    asm volatile("ldmatrix.sync.aligned.m8n8.x4.trans.shared.b16 {%0,%1,%2,%3}, [%4];"
                 : "=r"(r0), "=r"(r1), "=r"(r2), "=r"(r3) : "r"(addr));
}
__device__ __forceinline__ void mma16816(float* c, const uint32_t* a, const uint32_t* b) {
    asm volatile(
        "mma.sync.aligned.m16n8k16.row.col.f32.bf16.bf16.f32 "
        "{%0,%1,%2,%3},{%4,%5,%6,%7},{%8,%9},{%0,%1,%2,%3};"
        : "+f"(c[0]), "+f"(c[1]), "+f"(c[2]), "+f"(c[3])
        : "r"(a[0]), "r"(a[1]), "r"(a[2]), "r"(a[3]), "r"(b[0]), "r"(b[1]));
}
__device__ __forceinline__ void cpasync16(uint32_t smem, const void* g) {
    asm volatile("cp.async.cg.shared.global [%0], [%1], 16;" :: "r"(smem), "l"(g));
}
#define CP_COMMIT() asm volatile("cp.async.commit_group;" ::: "memory")
#define CP_WAIT1()  asm volatile("cp.async.wait_group 1;" ::: "memory")
#define CP_WAIT0()  asm volatile("cp.async.wait_group 0;" ::: "memory")

__device__ __forceinline__ uint32_t bpack(float x, float y) {
    __nv_bfloat162 t = __floats2bfloat162_rn(x, y);
    return *(uint32_t*)&t;
}
__device__ __forceinline__ uint32_t bpack_lo(float x, float y, uint32_t hi) {
    __nv_bfloat162 h = *(__nv_bfloat162*)&hi;
    return bpack(x - __bfloat162float(h.x), y - __bfloat162float(h.y));
}

// ---------------- 1. CPB MLP ----------------
__global__ void cpb_kernel(const float* __restrict__ tb, const float* __restrict__ w1,
                           const float* __restrict__ b1, const float* __restrict__ w2) {
    int r = blockIdx.x;
    float c0 = tb[r * 3 + 0], c1 = tb[r * 3 + 1], c2 = tb[r * 3 + 2];
    float acc[HH] = {0.f, 0.f, 0.f, 0.f, 0.f, 0.f};
    for (int j = threadIdx.x; j < 512; j += 128) {
        float hv = fmaf(c0, w1[j * 3 + 0], fmaf(c1, w1[j * 3 + 1], fmaf(c2, w1[j * 3 + 2], b1[j])));
        hv = fmaxf(hv, 0.f);
#pragma unroll
        for (int h = 0; h < HH; h++) acc[h] = fmaf(hv, w2[h * 512 + j], acc[h]);
    }
    __shared__ float red[HH][128];
#pragma unroll
    for (int h = 0; h < HH; h++) red[h][threadIdx.x] = acc[h];
    __syncthreads();
    for (int s = 64; s > 0; s >>= 1) {
        if (threadIdx.x < s) {
#pragma unroll
            for (int h = 0; h < HH; h++) red[h][threadIdx.x] += red[h][threadIdx.x + s];
        }
        __syncthreads();
    }
    if (threadIdx.x < HH) {
        float v = red[threadIdx.x][0];
        g_tbl[r * HH + threadIdx.x] = 16.f / (1.f + __expf(-v));
    }
}

// ---------------- 2. bias gather ----------------
__global__ void gather_kernel(const int* __restrict__ rel_index) {
    int ij = blockIdx.x * 256 + threadIdx.x;
    int id = rel_index[ij];
#pragma unroll
    for (int h = 0; h < HH; h++)
        g_bias[h * (NT * NT) + ij] = g_tbl[id * HH + h];
}

// ---------------- expansion kernels ----------------
__global__ void expand_a_kernel(const float* __restrict__ src) {  // x -> g_xE [hi|hi|lo]
    int i = blockIdx.x * 256 + threadIdx.x;
    float a = src[i];
    __nv_bfloat16 hi = __float2bfloat16(a);
    __nv_bfloat16 lo = __float2bfloat16(a - __bfloat162float(hi));
    int m = i / CC, k = i - m * CC;
    size_t o = (size_t)m * KE + k;
    g_xE[o] = hi; g_xE[o + CC] = hi; g_xE[o + 2 * CC] = lo;
}
template <int WHICH>
__global__ void expand_b_kernel(const float* __restrict__ src) {
    int i = blockIdx.x * 256 + threadIdx.x;
    float a = src[i];
    __nv_bfloat16 hi = __float2bfloat16(a);
    __nv_bfloat16 lo = __float2bfloat16(a - __bfloat162float(hi));
    int n = i / CC, k = i - n * CC;
    size_t o = (size_t)n * KE + k;
    __nv_bfloat16* dst = (WHICH == 0) ? g_wqkvE : g_wprojE;
    dst[o] = hi; dst[o + CC] = lo; dst[o + 2 * CC] = hi;
}

// ---------------- mma.sync GEMM: block 128(M) x 64(N), K'=576, cp.async 2-stage ----------------
template <int MODE>
__global__ void __launch_bounds__(256) mma_gemm(const float* __restrict__ bq,
                                                const float* __restrict__ bv,
                                                const float* __restrict__ lsc,
                                                float* __restrict__ Cout) {
    __shared__ __align__(128) unsigned char smem_all[49152];

    const int tid = threadIdx.x;
    const int wid = tid >> 5, lane = tid & 31;
    const int wm = wid >> 1, wn = wid & 1;
    const int m0 = blockIdx.y * 128;
    const int n0 = blockIdx.x * 64;

    const __nv_bfloat16* AE = (MODE == 0) ? g_xE : g_attE;
    const __nv_bfloat16* BE = (MODE == 0) ? g_wqkvE : g_wprojE;

    float acc[2][4][4];
#pragma unroll
    for (int t = 0; t < 2; t++)
#pragma unroll
        for (int nt = 0; nt < 4; nt++)
#pragma unroll
            for (int j = 0; j < 4; j++) acc[t][nt][j] = 0.f;

    const int li = lane & 7, lg = lane >> 3;
    const uint32_t sAu = s2u(smem_all), sBu = s2u(smem_all + 32768);
    const int rowA0 = wm * 32 + li + (lg & 1) * 8;
    const int chA = lg >> 1;
    const int rowB0 = wn * 32 + li + (lg >> 1) * 8;
    const int chB = lg & 1;

    const int grow = tid >> 3, gseg = tid & 7;

#define GSTAGE(c, buf) { \
        uint32_t aB = sAu + (buf) * 16384; \
        uint32_t bB = sBu + (buf) * 8192;  \
        _Pragma("unroll") \
        for (int it = 0; it < 4; it++) { \
            int row = grow + it * 32; \
            cpasync16(aB + SWZ(row * 128 + gseg * 16), \
                      AE + (size_t)(m0 + row) * KE + (c) * 64 + gseg * 8); \
        } \
        _Pragma("unroll") \
        for (int it = 0; it < 2; it++) { \
            int row = grow + it * 32; \
            cpasync16(bB + SWZ(row * 128 + gseg * 16), \
                      BE + (size_t)(n0 + row) * KE + (c) * 64 + gseg * 8); \
        } \
        CP_COMMIT(); }

    GSTAGE(0, 0);

    for (int c = 0; c < 9; c++) {
        __syncthreads();
        if (c < 8) { GSTAGE(c + 1, (c + 1) & 1); CP_WAIT1(); }
        else CP_WAIT0();
        __syncthreads();

        uint32_t aB = sAu + (c & 1) * 16384;
        uint32_t bB = sBu + (c & 1) * 8192;
#pragma unroll
        for (int s = 0; s < 4; s++) {
            uint32_t a[2][4], b[2][4];
#pragma unroll
            for (int t = 0; t < 2; t++) {
                int row = rowA0 + t * 16;
                uint32_t addr = aB + row * 128 + (((2 * s + chA) ^ (row & 7)) << 4);
                ldsm4(a[t][0], a[t][1], a[t][2], a[t][3], addr);
            }
#pragma unroll
            for (int p = 0; p < 2; p++) {
                int row = rowB0 + p * 16;
                uint32_t addr = bB + row * 128 + (((2 * s + chB) ^ (row & 7)) << 4);
                ldsm4(b[p][0], b[p][1], b[p][2], b[p][3], addr);
            }
#pragma unroll
            for (int t = 0; t < 2; t++)
#pragma unroll
                for (int nt = 0; nt < 4; nt++)
                    mma16816(acc[t][nt], a[t], &b[nt >> 1][(nt & 1) * 2]);
        }
    }
#undef GSTAGE

    const int nglob = n0 + wn * 32;
    const int qid = lane & 3;
    if (MODE == 0) {
        const int s = nglob / 192;
        const int rem = nglob - s * 192;
        const int h = rem >> 5;
        float mulq = 0.f;
        if (s == 0) mulq = __expf(fminf(lsc[h], 4.605170186f));
#pragma unroll
        for (int t = 0; t < 2; t++) {
#pragma unroll
            for (int half = 0; half < 2; half++) {
                int mrow = m0 + wm * 32 + t * 16 + half * 8 + (lane >> 2);
                float f[8];
#pragma unroll
                for (int nt = 0; nt < 4; nt++) {
                    int d0 = nt * 8 + qid * 2;
                    float b0 = (s == 0) ? bq[rem + d0] : ((s == 2) ? bv[rem + d0] : 0.f);
                    float b1 = (s == 0) ? bq[rem + d0 + 1] : ((s == 2) ? bv[rem + d0 + 1] : 0.f);
                    f[nt * 2 + 0] = acc[t][nt][half * 2 + 0] + b0;
                    f[nt * 2 + 1] = acc[t][nt][half * 2 + 1] + b1;
                }
                float mul = 1.f;
                if (s < 2) {
                    float ss = 0.f;
#pragma unroll
                    for (int j = 0; j < 8; j++) ss = fmaf(f[j], f[j], ss);
                    ss += __shfl_xor_sync(0xffffffffu, ss, 1);
                    ss += __shfl_xor_sync(0xffffffffu, ss, 2);
                    mul = 1.f / fmaxf(sqrtf(ss), 1e-12f);
                    if (s == 0) mul *= mulq;
                }
                const int bb = mrow >> 9, nr = mrow & 511;
                if (s == 0) {
                    float* op = g_q + ((((size_t)bb * HH + h) << 9) + nr) * HD;
#pragma unroll
                    for (int nt = 0; nt < 4; nt++) {
                        int d0 = nt * 8 + qid * 2;
                        *(float2*)(op + d0) = make_float2(f[nt * 2] * mul, f[nt * 2 + 1] * mul);
                    }
                } else {
                    unsigned char* op = (s == 1 ? g_kE : g_vE) +
                                        ((((size_t)bb * HH + h) << 9) + nr) * 128;
#pragma unroll
                    for (int nt = 0; nt < 4; nt++) {
                        int d0 = nt * 8 + qid * 2;
                        float a0 = f[nt * 2] * mul, a1 = f[nt * 2 + 1] * mul;
                        uint32_t hi = bpack(a0, a1);
                        uint32_t lo = bpack_lo(a0, a1, hi);
                        *(uint32_t*)(op + d0 * 2) = hi;
                        *(uint32_t*)(op + 64 + d0 * 2) = lo;
                    }
                }
            }
        }
    } else {
#pragma unroll
        for (int t = 0; t < 2; t++) {
#pragma unroll
            for (int half = 0; half < 2; half++) {
                int mrow = m0 + wm * 32 + t * 16 + half * 8 + (lane >> 2);
                float* op = Cout + (size_t)mrow * CC + nglob;
#pragma unroll
                for (int nt = 0; nt < 4; nt++) {
                    int d0 = nt * 8 + qid * 2;
                    float pb0 = bq[nglob + d0], pb1 = bq[nglob + d0 + 1];
                    *(float2*)(op + d0) = make_float2(acc[t][nt][half * 2 + 0] + pb0,
                                                      acc[t][nt][half * 2 + 1] + pb1);
                }
            }
        }
    }
}

// ---------------- tensor-core flash attention (cp.async K/V, double-buffered) ----------------
__global__ void __launch_bounds__(256) attn_mma(const float* __restrict__ mask) {
    const int b = blockIdx.z, h = blockIdx.y;
    const int i0 = blockIdx.x * 128;
    const int w = b & (NWIN - 1);
    const int tid = threadIdx.x, wid = tid >> 5, lane = tid & 31;
    const int qd = lane & 3, r = lane >> 2;

    __shared__ __align__(16) unsigned char sK[2][64 * 144];
    __shared__ __align__(16) unsigned char sV[2][64 * 144];
    const uint32_t sKu = s2u(sK), sVu = s2u(sV);

    const unsigned char* kgE = g_kE + (((size_t)(b * HH + h)) << 9) * 128;
    const unsigned char* vgE = g_vE + (((size_t)(b * HH + h)) << 9) * 128;
    const int crow = tid >> 2, cs0 = (tid & 3) * 2;

#define CPKV(jt, buf) { \
        const unsigned char* kr = kgE + (size_t)((jt) * 64 + crow) * 128 + cs0 * 16; \
        const unsigned char* vr = vgE + (size_t)((jt) * 64 + crow) * 128 + cs0 * 16; \
        uint32_t kd = sKu + (buf) * 9216 + crow * 144 + cs0 * 16; \
        uint32_t vd = sVu + (buf) * 9216 + crow * 144 + cs0 * 16; \
        cpasync16(kd, kr); cpasync16(kd + 16, kr + 16); \
        cpasync16(vd, vr); cpasync16(vd + 16, vr + 16); \
        CP_COMMIT(); }

    CPKV(0, 0);

    // ---- Q fragments (hi/lo) from fp32 g_q (overlaps first K/V copy) ----
    const int rowg = i0 + wid * 16 + r;
    const float* qrowA = g_q + (((size_t)(b * HH + h) << 9) + rowg) * HD;
    const float* qrowB = qrowA + 8 * HD;
    uint32_t Ahi[2][4], Alo[2][4];
#pragma unroll
    for (int c = 0; c < 2; c++) {
        float2 fa0 = *(const float2*)(qrowA + 2 * qd + 16 * c);
        float2 fb0 = *(const float2*)(qrowB + 2 * qd + 16 * c);
        float2 fa1 = *(const float2*)(qrowA + 2 * qd + 16 * c + 8);
        float2 fb1 = *(const float2*)(qrowB + 2 * qd + 16 * c + 8);
        Ahi[c][0] = bpack(fa0.x, fa0.y); Alo[c][0] = bpack_lo(fa0.x, fa0.y, Ahi[c][0]);
        Ahi[c][1] = bpack(fb0.x, fb0.y); Alo[c][1] = bpack_lo(fb0.x, fb0.y, Ahi[c][1]);
        Ahi[c][2] = bpack(fa1.x, fa1.y); Alo[c][2] = bpack_lo(fa1.x, fa1.y, Ahi[c][2]);
        Ahi[c][3] = bpack(fb1.x, fb1.y); Alo[c][3] = bpack_lo(fb1.x, fb1.y, Ahi[c][3]);
    }

    const int li = lane & 7, lg = lane >> 3;
    const uint32_t kbase = sKu + (((lg >> 1) * 8 + li) * 144) + (lg & 1) * 16;
    const uint32_t vbase = sVu + (((lg & 1) * 8 + li) * 144) + (lg >> 1) * 16;

    const float* pb = g_bias + ((size_t)(h * NT + rowg)) * NT + 2 * qd;
    const float* pm = mask + ((size_t)(w * NT + rowg)) * NT + 2 * qd;

    float O[4][4];
#pragma unroll
    for (int j = 0; j < 4; j++)
#pragma unroll
        for (int u = 0; u < 4; u++) O[j][u] = 0.f;
    float m0v = -1e30f, m1v = -1e30f, lsum0 = 0.f, lsum1 = 0.f;

    for (int jt = 0; jt < 8; jt++) {
        const int buf = jt & 1;
        CP_WAIT0();
        __syncthreads();                     // tile jt data visible; prior reads of buf^1 done
        if (jt < 7) CPKV(jt + 1, buf ^ 1);   // prefetch next tile behind this tile's compute

        // ---- init S with bias + mask ----
        float s[8][4];
#pragma unroll
        for (int j = 0; j < 8; j++) {
            int off = jt * 64 + j * 8;
            float2 bA = *(const float2*)(pb + off);
            float2 bB = *(const float2*)(pb + 8 * NT + off);
            float2 mA = *(const float2*)(pm + off);
            float2 mB = *(const float2*)(pm + 8 * NT + off);
            s[j][0] = bA.x + mA.x; s[j][1] = bA.y + mA.y;
            s[j][2] = bB.x + mB.x; s[j][3] = bB.y + mB.y;
        }

        // ---- S += Qe . Ke^T over 64 keys ----
#pragma unroll
        for (int jp = 0; jp < 4; jp++) {
            uint32_t h0[4], h1[4], l0r[4], l1r[4];
            uint32_t base = kbase + buf * 9216 + jp * 16 * 144;
            ldsm4(h0[0], h0[1], h0[2], h0[3], base + 0);
            ldsm4(h1[0], h1[1], h1[2], h1[3], base + 32);
            ldsm4(l0r[0], l0r[1], l0r[2], l0r[3], base + 64);
            ldsm4(l1r[0], l1r[1], l1r[2], l1r[3], base + 96);
            mma16816(s[2 * jp],     Ahi[0], h0 + 0);  mma16816(s[2 * jp],     Ahi[1], h1 + 0);
            mma16816(s[2 * jp],     Ahi[0], l0r + 0); mma16816(s[2 * jp],     Ahi[1], l1r + 0);
            mma16816(s[2 * jp],     Alo[0], h0 + 0);  mma16816(s[2 * jp],     Alo[1], h1 + 0);
            mma16816(s[2 * jp + 1], Ahi[0], h0 + 2);  mma16816(s[2 * jp + 1], Ahi[1], h1 + 2);
            mma16816(s[2 * jp + 1], Ahi[0], l0r + 2); mma16816(s[2 * jp + 1], Ahi[1], l1r + 2);
            mma16816(s[2 * jp + 1], Alo[0], h0 + 2);  mma16816(s[2 * jp + 1], Alo[1], h1 + 2);
        }

        // ---- online softmax ----
        float tm0 = -1e30f, tm1 = -1e30f;
#pragma unroll
        for (int j = 0; j < 8; j++) {
            tm0 = fmaxf(tm0, fmaxf(s[j][0], s[j][1]));
            tm1 = fmaxf(tm1, fmaxf(s[j][2], s[j][3]));
        }
        tm0 = fmaxf(tm0, __shfl_xor_sync(0xffffffffu, tm0, 1));
        tm0 = fmaxf(tm0, __shfl_xor_sync(0xffffffffu, tm0, 2));
        tm1 = fmaxf(tm1, __shfl_xor_sync(0xffffffffu, tm1, 1));
        tm1 = fmaxf(tm1, __shfl_xor_sync(0xffffffffu, tm1, 2));
        float mn0 = fmaxf(m0v, tm0), mn1 = fmaxf(m1v, tm1);
        float c0 = __expf(m0v - mn0), c1 = __expf(m1v - mn1);
        m0v = mn0; m1v = mn1;
        lsum0 *= c0; lsum1 *= c1;
#pragma unroll
        for (int j = 0; j < 4; j++) {
            O[j][0] *= c0; O[j][1] *= c0; O[j][2] *= c1; O[j][3] *= c1;
        }
#pragma unroll
        for (int j = 0; j < 8; j++) {
            s[j][0] = __expf(s[j][0] - mn0); s[j][1] = __expf(s[j][1] - mn0);
            s[j][2] = __expf(s[j][2] - mn1); s[j][3] = __expf(s[j][3] - mn1);
            lsum0 += s[j][0] + s[j][1];
            lsum1 += s[j][2] + s[j][3];
        }

        // ---- P fragments (hi/lo) ----
        uint32_t Phi[4][4], Plo[4][4];
#pragma unroll
        for (int c = 0; c < 4; c++) {
            Phi[c][0] = bpack(s[2 * c][0], s[2 * c][1]);
            Plo[c][0] = bpack_lo(s[2 * c][0], s[2 * c][1], Phi[c][0]);
            Phi[c][1] = bpack(s[2 * c][2], s[2 * c][3]);
            Plo[c][1] = bpack_lo(s[2 * c][2], s[2 * c][3], Phi[c][1]);
            Phi[c][2] = bpack(s[2 * c + 1][0], s[2 * c + 1][1]);
            Plo[c][2] = bpack_lo(s[2 * c + 1][0], s[2 * c + 1][1], Phi[c][2]);
            Phi[c][3] = bpack(s[2 * c + 1][2], s[2 * c + 1][3]);
            Plo[c][3] = bpack_lo(s[2 * c + 1][2], s[2 * c + 1][3], Phi[c][3]);
        }

        // ---- O += P . V  (3-product) ----
#pragma unroll
        for (int c = 0; c < 4; c++) {
#pragma unroll
            for (int jd = 0; jd < 2; jd++) {
                uint32_t vh[4], vl[4];
                uint32_t base = vbase + buf * 9216 + c * 16 * 144 + jd * 32;
                ldsm4t(vh[0], vh[1], vh[2], vh[3], base);
                ldsm4t(vl[0], vl[1], vl[2], vl[3], base + 64);
                mma16816(O[2 * jd],     Phi[c], vh + 0);
                mma16816(O[2 * jd],     Plo[c], vh + 0);
                mma16816(O[2 * jd],     Phi[c], vl + 0);
                mma16816(O[2 * jd + 1], Phi[c], vh + 2);
                mma16816(O[2 * jd + 1], Plo[c], vh + 2);
                mma16816(O[2 * jd + 1], Phi[c], vl + 2);
            }
        }
    }
#undef CPKV

    // ---- epilogue ----
    lsum0 += __shfl_xor_sync(0xffffffffu, lsum0, 1);
    lsum0 += __shfl_xor_sync(0xffffffffu, lsum0, 2);
    lsum1 += __shfl_xor_sync(0xffffffffu, lsum1, 1);
    lsum1 += __shfl_xor_sync(0xffffffffu, lsum1, 2);
    float inv0 = 1.f / lsum0, inv1 = 1.f / lsum1;

    __nv_bfloat16* baseA = g_attE + (size_t)(b * NT + rowg) * KE + h * HD + 2 * qd;
    __nv_bfloat16* baseB = baseA + (size_t)8 * KE;
#pragma unroll
    for (int j = 0; j < 4; j++) {
        int col = j * 8;
        uint32_t hiA = bpack(O[j][0] * inv0, O[j][1] * inv0);
        uint32_t loA = bpack_lo(O[j][0] * inv0, O[j][1] * inv0, hiA);
        *(uint32_t*)(baseA + col)       = hiA;
        *(uint32_t*)(baseA + col + CC)  = hiA;
        *(uint32_t*)(baseA + col + 2 * CC) = loA;
        uint32_t hiB = bpack(O[j][2] * inv1, O[j][3] * inv1);
        uint32_t loB = bpack_lo(O[j][2] * inv1, O[j][3] * inv1, hiB);
        *(uint32_t*)(baseB + col)       = hiB;
        *(uint32_t*)(baseB + col + CC)  = hiB;
        *(uint32_t*)(baseB + col + 2 * CC) = loB;
    }
}

// ---------------- launch ----------------
extern "C" void kernel_launch(void* const* d_in, const int* in_sizes, int n_in,
                              void* d_out, int out_size) {
    const float* x           = (const float*)d_in[0];
    const float* mask        = (const float*)d_in[1];
    const float* qkv_w       = (const float*)d_in[2];
    const float* q_bias      = (const float*)d_in[3];
    const float* v_bias      = (const float*)d_in[4];
    const float* logit_scale = (const float*)d_in[5];
    const float* cpb_w1      = (const float*)d_in[6];
    const float* cpb_b1      = (const float*)d_in[7];
    const float* cpb_w2      = (const float*)d_in[8];
    const float* proj_w      = (const float*)d_in[9];
    const float* proj_b      = (const float*)d_in[10];
    const float* rel_table   = (const float*)d_in[11];
    const int*   rel_index   = (const int*)d_in[12];
    float* out = (float*)d_out;

    cpb_kernel<<<TBL, 128>>>(rel_table, cpb_w1, cpb_b1, cpb_w2);
    gather_kernel<<<(NT * NT) / 256, 256>>>(rel_index);
    expand_a_kernel<<<(BW * NT * CC) / 256, 256>>>(x);
    expand_b_kernel<0><<<(3 * CC * CC) / 256, 256>>>(qkv_w);
    expand_b_kernel<1><<<(CC * CC) / 256, 256>>>(proj_w);
    mma_gemm<0><<<dim3(9, 256), 256>>>(q_bias, v_bias, logit_scale, nullptr);
    attn_mma<<<dim3(4, HH, BW), 256>>>(mask);
    mma_gemm<1><<<dim3(3, 256), 256>>>(proj_b, nullptr, nullptr, out);
}

// round 7
// speedup vs baseline: 3.2083x; 1.2539x over previous
#include <cuda_runtime.h>
#include <cuda_fp16.h>
#include <cstdint>

// ---------------- problem constants ----------------
#define BW   64
#define NT   512
#define CC   192
#define HH   6
#define HD   32
#define NWIN 16
#define TBL  3375
#define KE2  384           // expanded K = 2*192 (fp16 hi|lo)

// ---------------- device scratch ----------------
__device__ float g_tbl[TBL * HH];
__device__ float g_bias[HH * NT * NT];
__device__ float g_q[BW * HH * NT * HD];
// k/v stored as fp16 hi only: 32 halfs (64B) per key
__device__ __half g_kE[(size_t)BW * HH * NT * 32];
__device__ __half g_vE[(size_t)BW * HH * NT * 32];
__device__ __half g_xE[(size_t)BW * NT * KE2];     // x expanded [hi|lo]
__device__ __half g_attE[(size_t)BW * NT * KE2];   // attn out expanded [hi|lo]
__device__ __half g_wqkvE[3 * CC * KE2];           // qkv_w expanded [hi|hi]
__device__ __half g_wprojE[CC * KE2];              // proj_w expanded [hi|hi]

#define SWZ(o) ((o) ^ (((o) >> 3) & 0x70))

__device__ __forceinline__ uint32_t s2u(const void* p) {
    return (uint32_t)__cvta_generic_to_shared(p);
}
__device__ __forceinline__ void ldsm4(uint32_t& r0, uint32_t& r1, uint32_t& r2, uint32_t& r3,
                                      uint32_t addr) {
    asm volatile("ldmatrix.sync.aligned.m8n8.x4.shared.b16 {%0,%1,%2,%3}, [%4];"
                 : "=r"(r0), "=r"(r1), "=r"(r2), "=r"(r3) : "r"(addr));
}
__device__ __forceinline__ void ldsm4t(uint32_t& r0, uint32_t& r1, uint32_t& r2, uint32_t& r3,
                                       uint32_t addr) {
    asm volatile("ldmatrix.sync.aligned.m8n8.x4.trans.shared.b16 {%0,%1,%2,%3}, [%4];"
                 : "=r"(r0), "=r"(r1), "=r"(r2), "=r"(r3) : "r"(addr));
}
__device__ __forceinline__ void mma16816(float* c, const uint32_t* a, const uint32_t* b) {
    asm volatile(
        "mma.sync.aligned.m16n8k16.row.col.f32.f16.f16.f32 "
        "{%0,%1,%2,%3},{%4,%5,%6,%7},{%8,%9},{%0,%1,%2,%3};"
        : "+f"(c[0]), "+f"(c[1]), "+f"(c[2]), "+f"(c[3])
        : "r"(a[0]), "r"(a[1]), "r"(a[2]), "r"(a[3]), "r"(b[0]), "r"(b[1]));
}
__device__ __forceinline__ void cpasync16(uint32_t smem, const void* g) {
    asm volatile("cp.async.cg.shared.global [%0], [%1], 16;" :: "r"(smem), "l"(g));
}
#define CP_COMMIT() asm volatile("cp.async.commit_group;" ::: "memory")
#define CP_WAIT1()  asm volatile("cp.async.wait_group 1;" ::: "memory")
#define CP_WAIT0()  asm volatile("cp.async.wait_group 0;" ::: "memory")

__device__ __forceinline__ uint32_t hpack(float x, float y) {
    __half2 t = __floats2half2_rn(x, y);
    return *(uint32_t*)&t;
}
__device__ __forceinline__ uint32_t hpack_lo(float x, float y, uint32_t hi) {
    __half2 h = *(__half2*)&hi;
    return hpack(x - __half2float(h.x), y - __half2float(h.y));
}

// ---------------- 1. CPB MLP ----------------
__global__ void cpb_kernel(const float* __restrict__ tb, const float* __restrict__ w1,
                           const float* __restrict__ b1, const float* __restrict__ w2) {
    int r = blockIdx.x;
    float c0 = tb[r * 3 + 0], c1 = tb[r * 3 + 1], c2 = tb[r * 3 + 2];
    float acc[HH] = {0.f, 0.f, 0.f, 0.f, 0.f, 0.f};
    for (int j = threadIdx.x; j < 512; j += 128) {
        float hv = fmaf(c0, w1[j * 3 + 0], fmaf(c1, w1[j * 3 + 1], fmaf(c2, w1[j * 3 + 2], b1[j])));
        hv = fmaxf(hv, 0.f);
#pragma unroll
        for (int h = 0; h < HH; h++) acc[h] = fmaf(hv, w2[h * 512 + j], acc[h]);
    }
    __shared__ float red[HH][128];
#pragma unroll
    for (int h = 0; h < HH; h++) red[h][threadIdx.x] = acc[h];
    __syncthreads();
    for (int s = 64; s > 0; s >>= 1) {
        if (threadIdx.x < s) {
#pragma unroll
            for (int h = 0; h < HH; h++) red[h][threadIdx.x] += red[h][threadIdx.x + s];
        }
        __syncthreads();
    }
    if (threadIdx.x < HH) {
        float v = red[threadIdx.x][0];
        g_tbl[r * HH + threadIdx.x] = 16.f / (1.f + __expf(-v));
    }
}

// ---------------- 2. bias gather ----------------
__global__ void gather_kernel(const int* __restrict__ rel_index) {
    int ij = blockIdx.x * 256 + threadIdx.x;
    int id = rel_index[ij];
#pragma unroll
    for (int h = 0; h < HH; h++)
        g_bias[h * (NT * NT) + ij] = g_tbl[id * HH + h];
}

// ---------------- expansion kernels ----------------
__global__ void expand_a_kernel(const float* __restrict__ src) {  // x -> g_xE [hi|lo]
    int i = blockIdx.x * 256 + threadIdx.x;
    float a = src[i];
    __half hi = __float2half_rn(a);
    __half lo = __float2half_rn(a - __half2float(hi));
    int m = i / CC, k = i - m * CC;
    size_t o = (size_t)m * KE2 + k;
    g_xE[o] = hi; g_xE[o + CC] = lo;
}
template <int WHICH>   // weights: [hi|hi]
__global__ void expand_b_kernel(const float* __restrict__ src) {
    int i = blockIdx.x * 256 + threadIdx.x;
    float a = src[i];
    __half hi = __float2half_rn(a);
    int n = i / CC, k = i - n * CC;
    size_t o = (size_t)n * KE2 + k;
    __half* dst = (WHICH == 0) ? g_wqkvE : g_wprojE;
    dst[o] = hi; dst[o + CC] = hi;
}

// ---------------- mma.sync GEMM: block 128(M) x 64(N), K'=384, cp.async 2-stage ----------------
template <int MODE>
__global__ void __launch_bounds__(256) mma_gemm(const float* __restrict__ bq,
                                                const float* __restrict__ bv,
                                                const float* __restrict__ lsc,
                                                float* __restrict__ Cout) {
    __shared__ __align__(128) unsigned char smem_all[49152];

    const int tid = threadIdx.x;
    const int wid = tid >> 5, lane = tid & 31;
    const int wm = wid >> 1, wn = wid & 1;
    const int m0 = blockIdx.y * 128;
    const int n0 = blockIdx.x * 64;

    const __half* AE = (MODE == 0) ? g_xE : g_attE;
    const __half* BE = (MODE == 0) ? g_wqkvE : g_wprojE;

    float acc[2][4][4];
#pragma unroll
    for (int t = 0; t < 2; t++)
#pragma unroll
        for (int nt = 0; nt < 4; nt++)
#pragma unroll
            for (int j = 0; j < 4; j++) acc[t][nt][j] = 0.f;

    const int li = lane & 7, lg = lane >> 3;
    const uint32_t sAu = s2u(smem_all), sBu = s2u(smem_all + 32768);
    const int rowA0 = wm * 32 + li + (lg & 1) * 8;
    const int chA = lg >> 1;
    const int rowB0 = wn * 32 + li + (lg >> 1) * 8;
    const int chB = lg & 1;

    const int grow = tid >> 3, gseg = tid & 7;

#define GSTAGE(c, buf) { \
        uint32_t aB = sAu + (buf) * 16384; \
        uint32_t bB = sBu + (buf) * 8192;  \
        _Pragma("unroll") \
        for (int it = 0; it < 4; it++) { \
            int row = grow + it * 32; \
            cpasync16(aB + SWZ(row * 128 + gseg * 16), \
                      AE + (size_t)(m0 + row) * KE2 + (c) * 64 + gseg * 8); \
        } \
        _Pragma("unroll") \
        for (int it = 0; it < 2; it++) { \
            int row = grow + it * 32; \
            cpasync16(bB + SWZ(row * 128 + gseg * 16), \
                      BE + (size_t)(n0 + row) * KE2 + (c) * 64 + gseg * 8); \
        } \
        CP_COMMIT(); }

    GSTAGE(0, 0);

    for (int c = 0; c < 6; c++) {
        __syncthreads();
        if (c < 5) { GSTAGE(c + 1, (c + 1) & 1); CP_WAIT1(); }
        else CP_WAIT0();
        __syncthreads();

        uint32_t aB = sAu + (c & 1) * 16384;
        uint32_t bB = sBu + (c & 1) * 8192;
#pragma unroll
        for (int s = 0; s < 4; s++) {
            uint32_t a[2][4], b[2][4];
#pragma unroll
            for (int t = 0; t < 2; t++) {
                int row = rowA0 + t * 16;
                uint32_t addr = aB + row * 128 + (((2 * s + chA) ^ (row & 7)) << 4);
                ldsm4(a[t][0], a[t][1], a[t][2], a[t][3], addr);
            }
#pragma unroll
            for (int p = 0; p < 2; p++) {
                int row = rowB0 + p * 16;
                uint32_t addr = bB + row * 128 + (((2 * s + chB) ^ (row & 7)) << 4);
                ldsm4(b[p][0], b[p][1], b[p][2], b[p][3], addr);
            }
#pragma unroll
            for (int t = 0; t < 2; t++)
#pragma unroll
                for (int nt = 0; nt < 4; nt++)
                    mma16816(acc[t][nt], a[t], &b[nt >> 1][(nt & 1) * 2]);
        }
    }
#undef GSTAGE

    const int nglob = n0 + wn * 32;
    const int qid = lane & 3;
    if (MODE == 0) {
        const int s = nglob / 192;
        const int rem = nglob - s * 192;
        const int h = rem >> 5;
        float mulq = 0.f;
        if (s == 0) mulq = __expf(fminf(lsc[h], 4.605170186f));
#pragma unroll
        for (int t = 0; t < 2; t++) {
#pragma unroll
            for (int half = 0; half < 2; half++) {
                int mrow = m0 + wm * 32 + t * 16 + half * 8 + (lane >> 2);
                float f[8];
#pragma unroll
                for (int nt = 0; nt < 4; nt++) {
                    int d0 = nt * 8 + qid * 2;
                    float b0 = (s == 0) ? bq[rem + d0] : ((s == 2) ? bv[rem + d0] : 0.f);
                    float b1 = (s == 0) ? bq[rem + d0 + 1] : ((s == 2) ? bv[rem + d0 + 1] : 0.f);
                    f[nt * 2 + 0] = acc[t][nt][half * 2 + 0] + b0;
                    f[nt * 2 + 1] = acc[t][nt][half * 2 + 1] + b1;
                }
                float mul = 1.f;
                if (s < 2) {
                    float ss = 0.f;
#pragma unroll
                    for (int j = 0; j < 8; j++) ss = fmaf(f[j], f[j], ss);
                    ss += __shfl_xor_sync(0xffffffffu, ss, 1);
                    ss += __shfl_xor_sync(0xffffffffu, ss, 2);
                    mul = 1.f / fmaxf(sqrtf(ss), 1e-12f);
                    if (s == 0) mul *= mulq;
                }
                const int bb = mrow >> 9, nr = mrow & 511;
                if (s == 0) {
                    float* op = g_q + ((((size_t)bb * HH + h) << 9) + nr) * HD;
#pragma unroll
                    for (int nt = 0; nt < 4; nt++) {
                        int d0 = nt * 8 + qid * 2;
                        *(float2*)(op + d0) = make_float2(f[nt * 2] * mul, f[nt * 2 + 1] * mul);
                    }
                } else {
                    __half* op = (s == 1 ? g_kE : g_vE) +
                                 ((((size_t)bb * HH + h) << 9) + nr) * 32;
#pragma unroll
                    for (int nt = 0; nt < 4; nt++) {
                        int d0 = nt * 8 + qid * 2;
                        *(uint32_t*)(op + d0) = hpack(f[nt * 2] * mul, f[nt * 2 + 1] * mul);
                    }
                }
            }
        }
    } else {
#pragma unroll
        for (int t = 0; t < 2; t++) {
#pragma unroll
            for (int half = 0; half < 2; half++) {
                int mrow = m0 + wm * 32 + t * 16 + half * 8 + (lane >> 2);
                float* op = Cout + (size_t)mrow * CC + nglob;
#pragma unroll
                for (int nt = 0; nt < 4; nt++) {
                    int d0 = nt * 8 + qid * 2;
                    float pb0 = bq[nglob + d0], pb1 = bq[nglob + d0 + 1];
                    *(float2*)(op + d0) = make_float2(acc[t][nt][half * 2 + 0] + pb0,
                                                      acc[t][nt][half * 2 + 1] + pb1);
                }
            }
        }
    }
}

// ---------------- tensor-core flash attention (fp16, cp.async, double-buffered) ----------------
// K/V smem panel: 64 keys x 64B (fp16 hi only), row stride 80B (conflict-free ldsm).
#define PANEL 5120
__global__ void __launch_bounds__(256) attn_mma(const float* __restrict__ mask) {
    const int b = blockIdx.z, h = blockIdx.y;
    const int i0 = blockIdx.x * 128;
    const int w = b & (NWIN - 1);
    const int tid = threadIdx.x, wid = tid >> 5, lane = tid & 31;
    const int qd = lane & 3, r = lane >> 2;

    __shared__ __align__(16) unsigned char sK[2 * PANEL];
    __shared__ __align__(16) unsigned char sV[2 * PANEL];
    const uint32_t sKu = s2u(sK), sVu = s2u(sV);

    const __half* kgE = g_kE + (((size_t)(b * HH + h)) << 9) * 32;
    const __half* vgE = g_vE + (((size_t)(b * HH + h)) << 9) * 32;
    const int crow = tid >> 2, cseg = tid & 3;

#define CPKV(jt, buf) { \
        cpasync16(sKu + (buf) * PANEL + crow * 80 + cseg * 16, \
                  kgE + (size_t)((jt) * 64 + crow) * 32 + cseg * 8); \
        cpasync16(sVu + (buf) * PANEL + crow * 80 + cseg * 16, \
                  vgE + (size_t)((jt) * 64 + crow) * 32 + cseg * 8); \
        CP_COMMIT(); }

    CPKV(0, 0);

    // ---- Q fragments (hi/lo fp16) from fp32 g_q ----
    const int rowg = i0 + wid * 16 + r;
    const float* qrowA = g_q + (((size_t)(b * HH + h) << 9) + rowg) * HD;
    const float* qrowB = qrowA + 8 * HD;
    uint32_t Ahi[2][4], Alo[2][4];
#pragma unroll
    for (int c = 0; c < 2; c++) {
        float2 fa0 = *(const float2*)(qrowA + 2 * qd + 16 * c);
        float2 fb0 = *(const float2*)(qrowB + 2 * qd + 16 * c);
        float2 fa1 = *(const float2*)(qrowA + 2 * qd + 16 * c + 8);
        float2 fb1 = *(const float2*)(qrowB + 2 * qd + 16 * c + 8);
        Ahi[c][0] = hpack(fa0.x, fa0.y); Alo[c][0] = hpack_lo(fa0.x, fa0.y, Ahi[c][0]);
        Ahi[c][1] = hpack(fb0.x, fb0.y); Alo[c][1] = hpack_lo(fb0.x, fb0.y, Ahi[c][1]);
        Ahi[c][2] = hpack(fa1.x, fa1.y); Alo[c][2] = hpack_lo(fa1.x, fa1.y, Ahi[c][2]);
        Ahi[c][3] = hpack(fb1.x, fb1.y); Alo[c][3] = hpack_lo(fb1.x, fb1.y, Ahi[c][3]);
    }

    const int li = lane & 7, lg = lane >> 3;
    const uint32_t kbase = sKu + (((lg >> 1) * 8 + li) * 80) + (lg & 1) * 16;
    const uint32_t vbase = sVu + (((lg & 1) * 8 + li) * 80) + (lg >> 1) * 16;

    const float* pb = g_bias + ((size_t)(h * NT + rowg)) * NT + 2 * qd;
    const float* pm = mask + ((size_t)(w * NT + rowg)) * NT + 2 * qd;

    float O[4][4];
#pragma unroll
    for (int j = 0; j < 4; j++)
#pragma unroll
        for (int u = 0; u < 4; u++) O[j][u] = 0.f;
    float m0v = -1e30f, m1v = -1e30f, lsum0 = 0.f, lsum1 = 0.f;

    for (int jt = 0; jt < 8; jt++) {
        const int buf = jt & 1;
        CP_WAIT0();
        __syncthreads();
        if (jt < 7) CPKV(jt + 1, buf ^ 1);

        // ---- init S with bias + mask ----
        float s[8][4];
#pragma unroll
        for (int j = 0; j < 8; j++) {
            int off = jt * 64 + j * 8;
            float2 bA = *(const float2*)(pb + off);
            float2 bB = *(const float2*)(pb + 8 * NT + off);
            float2 mA = *(const float2*)(pm + off);
            float2 mB = *(const float2*)(pm + 8 * NT + off);
            s[j][0] = bA.x + mA.x; s[j][1] = bA.y + mA.y;
            s[j][2] = bB.x + mB.x; s[j][3] = bB.y + mB.y;
        }

        // ---- S += (qhi+qlo) . khi^T over 64 keys ----
#pragma unroll
        for (int jp = 0; jp < 4; jp++) {
            uint32_t h0[4], h1[4];
            uint32_t base = kbase + buf * PANEL + jp * 16 * 80;
            ldsm4(h0[0], h0[1], h0[2], h0[3], base + 0);
            ldsm4(h1[0], h1[1], h1[2], h1[3], base + 32);
            mma16816(s[2 * jp],     Ahi[0], h0 + 0);  mma16816(s[2 * jp],     Ahi[1], h1 + 0);
            mma16816(s[2 * jp],     Alo[0], h0 + 0);  mma16816(s[2 * jp],     Alo[1], h1 + 0);
            mma16816(s[2 * jp + 1], Ahi[0], h0 + 2);  mma16816(s[2 * jp + 1], Ahi[1], h1 + 2);
            mma16816(s[2 * jp + 1], Alo[0], h0 + 2);  mma16816(s[2 * jp + 1], Alo[1], h1 + 2);
        }

        // ---- online softmax ----
        float tm0 = -1e30f, tm1 = -1e30f;
#pragma unroll
        for (int j = 0; j < 8; j++) {
            tm0 = fmaxf(tm0, fmaxf(s[j][0], s[j][1]));
            tm1 = fmaxf(tm1, fmaxf(s[j][2], s[j][3]));
        }
        tm0 = fmaxf(tm0, __shfl_xor_sync(0xffffffffu, tm0, 1));
        tm0 = fmaxf(tm0, __shfl_xor_sync(0xffffffffu, tm0, 2));
        tm1 = fmaxf(tm1, __shfl_xor_sync(0xffffffffu, tm1, 1));
        tm1 = fmaxf(tm1, __shfl_xor_sync(0xffffffffu, tm1, 2));
        float mn0 = fmaxf(m0v, tm0), mn1 = fmaxf(m1v, tm1);
        float c0 = __expf(m0v - mn0), c1 = __expf(m1v - mn1);
        m0v = mn0; m1v = mn1;
        lsum0 *= c0; lsum1 *= c1;
#pragma unroll
        for (int j = 0; j < 4; j++) {
            O[j][0] *= c0; O[j][1] *= c0; O[j][2] *= c1; O[j][3] *= c1;
        }
#pragma unroll
        for (int j = 0; j < 8; j++) {
            s[j][0] = __expf(s[j][0] - mn0); s[j][1] = __expf(s[j][1] - mn0);
            s[j][2] = __expf(s[j][2] - mn1); s[j][3] = __expf(s[j][3] - mn1);
            lsum0 += s[j][0] + s[j][1];
            lsum1 += s[j][2] + s[j][3];
        }

        // ---- P fragments (hi/lo fp16) ----
        uint32_t Phi[4][4], Plo[4][4];
#pragma unroll
        for (int c = 0; c < 4; c++) {
            Phi[c][0] = hpack(s[2 * c][0], s[2 * c][1]);
            Plo[c][0] = hpack_lo(s[2 * c][0], s[2 * c][1], Phi[c][0]);
            Phi[c][1] = hpack(s[2 * c][2], s[2 * c][3]);
            Plo[c][1] = hpack_lo(s[2 * c][2], s[2 * c][3], Phi[c][1]);
            Phi[c][2] = hpack(s[2 * c + 1][0], s[2 * c + 1][1]);
            Plo[c][2] = hpack_lo(s[2 * c + 1][0], s[2 * c + 1][1], Phi[c][2]);
            Phi[c][3] = hpack(s[2 * c + 1][2], s[2 * c + 1][3]);
            Plo[c][3] = hpack_lo(s[2 * c + 1][2], s[2 * c + 1][3], Phi[c][3]);
        }

        // ---- O += (Phi+Plo) . vhi ----
#pragma unroll
        for (int c = 0; c < 4; c++) {
#pragma unroll
            for (int jd = 0; jd < 2; jd++) {
                uint32_t vh[4];
                uint32_t base = vbase + buf * PANEL + c * 16 * 80 + jd * 32;
                ldsm4t(vh[0], vh[1], vh[2], vh[3], base);
                mma16816(O[2 * jd],     Phi[c], vh + 0);
                mma16816(O[2 * jd],     Plo[c], vh + 0);
                mma16816(O[2 * jd + 1], Phi[c], vh + 2);
                mma16816(O[2 * jd + 1], Plo[c], vh + 2);
            }
        }
    }
#undef CPKV

    // ---- epilogue ----
    lsum0 += __shfl_xor_sync(0xffffffffu, lsum0, 1);
    lsum0 += __shfl_xor_sync(0xffffffffu, lsum0, 2);
    lsum1 += __shfl_xor_sync(0xffffffffu, lsum1, 1);
    lsum1 += __shfl_xor_sync(0xffffffffu, lsum1, 2);
    float inv0 = 1.f / lsum0, inv1 = 1.f / lsum1;

    __half* baseA = g_attE + (size_t)(b * NT + rowg) * KE2 + h * HD + 2 * qd;
    __half* baseB = baseA + (size_t)8 * KE2;
#pragma unroll
    for (int j = 0; j < 4; j++) {
        int col = j * 8;
        uint32_t hiA = hpack(O[j][0] * inv0, O[j][1] * inv0);
        uint32_t loA = hpack_lo(O[j][0] * inv0, O[j][1] * inv0, hiA);
        *(uint32_t*)(baseA + col)      = hiA;
        *(uint32_t*)(baseA + col + CC) = loA;
        uint32_t hiB = hpack(O[j][2] * inv1, O[j][3] * inv1);
        uint32_t loB = hpack_lo(O[j][2] * inv1, O[j][3] * inv1, hiB);
        *(uint32_t*)(baseB + col)      = hiB;
        *(uint32_t*)(baseB + col + CC) = loB;
    }
}

// ---------------- launch ----------------
extern "C" void kernel_launch(void* const* d_in, const int* in_sizes, int n_in,
                              void* d_out, int out_size) {
    const float* x           = (const float*)d_in[0];
    const float* mask        = (const float*)d_in[1];
    const float* qkv_w       = (const float*)d_in[2];
    const float* q_bias      = (const float*)d_in[3];
    const float* v_bias      = (const float*)d_in[4];
    const float* logit_scale = (const float*)d_in[5];
    const float* cpb_w1      = (const float*)d_in[6];
    const float* cpb_b1      = (const float*)d_in[7];
    const float* cpb_w2      = (const float*)d_in[8];
    const float* proj_w      = (const float*)d_in[9];
    const float* proj_b      = (const float*)d_in[10];
    const float* rel_table   = (const float*)d_in[11];
    const int*   rel_index   = (const int*)d_in[12];
    float* out = (float*)d_out;

    cpb_kernel<<<TBL, 128>>>(rel_table, cpb_w1, cpb_b1, cpb_w2);
    gather_kernel<<<(NT * NT) / 256, 256>>>(rel_index);
    expand_a_kernel<<<(BW * NT * CC) / 256, 256>>>(x);
    expand_b_kernel<0><<<(3 * CC * CC) / 256, 256>>>(qkv_w);
    expand_b_kernel<1><<<(CC * CC) / 256, 256>>>(proj_w);
    mma_gemm<0><<<dim3(9, 256), 256>>>(q_bias, v_bias, logit_scale, nullptr);
    attn_mma<<<dim3(4, HH, BW), 256>>>(mask);
    mma_gemm<1><<<dim3(3, 256), 256>>>(proj_b, nullptr, nullptr, out);
}

// round 8
// speedup vs baseline: 3.2818x; 1.0229x over previous
#include <cuda_runtime.h>
#include <cuda_fp16.h>
#include <cstdint>

// ---------------- problem constants ----------------
#define BW   64
#define NT   512
#define CC   192
#define HH   6
#define HD   32
#define NWIN 16
#define TBL  3375
#define KE2  384           // expanded K = 2*192 (fp16 hi|lo)

// ---------------- device scratch ----------------
__device__ float g_tbl[TBL * HH];
__device__ float g_bias[HH * NT * NT];
__device__ float g_q[BW * HH * NT * HD];
// k/v stored as fp16 hi only: 32 halfs (64B) per key
__device__ __half g_kE[(size_t)BW * HH * NT * 32];
__device__ __half g_vE[(size_t)BW * HH * NT * 32];
__device__ __half g_xE[(size_t)BW * NT * KE2];     // x expanded [hi|lo]
__device__ __half g_attE[(size_t)BW * NT * KE2];   // attn out expanded [hi|lo]
__device__ __half g_wqkvE[3 * CC * KE2];           // qkv_w expanded [hi|hi]
__device__ __half g_wprojE[CC * KE2];              // proj_w expanded [hi|hi]

#define SWZ(o) ((o) ^ (((o) >> 3) & 0x70))

__device__ __forceinline__ uint32_t s2u(const void* p) {
    return (uint32_t)__cvta_generic_to_shared(p);
}
__device__ __forceinline__ void ldsm4(uint32_t& r0, uint32_t& r1, uint32_t& r2, uint32_t& r3,
                                      uint32_t addr) {
    asm volatile("ldmatrix.sync.aligned.m8n8.x4.shared.b16 {%0,%1,%2,%3}, [%4];"
                 : "=r"(r0), "=r"(r1), "=r"(r2), "=r"(r3) : "r"(addr));
}
__device__ __forceinline__ void ldsm4t(uint32_t& r0, uint32_t& r1, uint32_t& r2, uint32_t& r3,
                                       uint32_t addr) {
    asm volatile("ldmatrix.sync.aligned.m8n8.x4.trans.shared.b16 {%0,%1,%2,%3}, [%4];"
                 : "=r"(r0), "=r"(r1), "=r"(r2), "=r"(r3) : "r"(addr));
}
__device__ __forceinline__ void mma16816(float* c, const uint32_t* a, const uint32_t* b) {
    asm volatile(
        "mma.sync.aligned.m16n8k16.row.col.f32.f16.f16.f32 "
        "{%0,%1,%2,%3},{%4,%5,%6,%7},{%8,%9},{%0,%1,%2,%3};"
        : "+f"(c[0]), "+f"(c[1]), "+f"(c[2]), "+f"(c[3])
        : "r"(a[0]), "r"(a[1]), "r"(a[2]), "r"(a[3]), "r"(b[0]), "r"(b[1]));
}
__device__ __forceinline__ void cpasync16(uint32_t smem, const void* g) {
    asm volatile("cp.async.cg.shared.global [%0], [%1], 16;" :: "r"(smem), "l"(g));
}
#define CP_COMMIT() asm volatile("cp.async.commit_group;" ::: "memory")
#define CP_WAIT0()  asm volatile("cp.async.wait_group 0;" ::: "memory")

__device__ __forceinline__ uint32_t hpack(float x, float y) {
    __half2 t = __floats2half2_rn(x, y);
    return *(uint32_t*)&t;
}
__device__ __forceinline__ uint32_t hpack_lo(float x, float y, uint32_t hi) {
    __half2 h = *(__half2*)&hi;
    return hpack(x - __half2float(h.x), y - __half2float(h.y));
}

// ---------------- 1. CPB MLP ----------------
__global__ void cpb_kernel(const float* __restrict__ tb, const float* __restrict__ w1,
                           const float* __restrict__ b1, const float* __restrict__ w2) {
    int r = blockIdx.x;
    float c0 = tb[r * 3 + 0], c1 = tb[r * 3 + 1], c2 = tb[r * 3 + 2];
    float acc[HH] = {0.f, 0.f, 0.f, 0.f, 0.f, 0.f};
    for (int j = threadIdx.x; j < 512; j += 128) {
        float hv = fmaf(c0, w1[j * 3 + 0], fmaf(c1, w1[j * 3 + 1], fmaf(c2, w1[j * 3 + 2], b1[j])));
        hv = fmaxf(hv, 0.f);
#pragma unroll
        for (int h = 0; h < HH; h++) acc[h] = fmaf(hv, w2[h * 512 + j], acc[h]);
    }
    __shared__ float red[HH][128];
#pragma unroll
    for (int h = 0; h < HH; h++) red[h][threadIdx.x] = acc[h];
    __syncthreads();
    for (int s = 64; s > 0; s >>= 1) {
        if (threadIdx.x < s) {
#pragma unroll
            for (int h = 0; h < HH; h++) red[h][threadIdx.x] += red[h][threadIdx.x + s];
        }
        __syncthreads();
    }
    if (threadIdx.x < HH) {
        float v = red[threadIdx.x][0];
        g_tbl[r * HH + threadIdx.x] = 16.f / (1.f + __expf(-v));
    }
}

// ---------------- 2. fused prep: expand_a + expand_b(qkv) + expand_b(proj) + gather ----------------
#define NB_XA   ((BW * NT * CC) / 256)        // 24576
#define NB_WQ   ((3 * CC * CC) / 256)         // 432
#define NB_WP   ((CC * CC) / 256)             // 144
#define NB_GA   ((NT * NT) / 256)             // 1024
__global__ void prep_kernel(const float* __restrict__ x, const float* __restrict__ qkv_w,
                            const float* __restrict__ proj_w, const int* __restrict__ rel_index) {
    int bid = blockIdx.x;
    if (bid < NB_XA) {
        int i = bid * 256 + threadIdx.x;
        float a = x[i];
        __half hi = __float2half_rn(a);
        __half lo = __float2half_rn(a - __half2float(hi));
        int m = i / CC, k = i - m * CC;
        size_t o = (size_t)m * KE2 + k;
        g_xE[o] = hi; g_xE[o + CC] = lo;
    } else if (bid < NB_XA + NB_WQ) {
        int i = (bid - NB_XA) * 256 + threadIdx.x;
        __half hi = __float2half_rn(qkv_w[i]);
        int n = i / CC, k = i - n * CC;
        size_t o = (size_t)n * KE2 + k;
        g_wqkvE[o] = hi; g_wqkvE[o + CC] = hi;
    } else if (bid < NB_XA + NB_WQ + NB_WP) {
        int i = (bid - NB_XA - NB_WQ) * 256 + threadIdx.x;
        __half hi = __float2half_rn(proj_w[i]);
        int n = i / CC, k = i - n * CC;
        size_t o = (size_t)n * KE2 + k;
        g_wprojE[o] = hi; g_wprojE[o + CC] = hi;
    } else {
        int ij = (bid - NB_XA - NB_WQ - NB_WP) * 256 + threadIdx.x;
        int id = rel_index[ij];
#pragma unroll
        for (int h = 0; h < HH; h++)
            g_bias[h * (NT * NT) + ij] = g_tbl[id * HH + h];
    }
}

// ---------------- mma.sync GEMM: block 128(M) x 64(N), K'=384, cp.async 2-stage ----------------
template <int MODE>
__global__ void __launch_bounds__(256) mma_gemm(const float* __restrict__ bq,
                                                const float* __restrict__ bv,
                                                const float* __restrict__ lsc,
                                                float* __restrict__ Cout) {
    __shared__ __align__(128) unsigned char smem_all[49152];

    const int tid = threadIdx.x;
    const int wid = tid >> 5, lane = tid & 31;
    const int wm = wid >> 1, wn = wid & 1;
    const int m0 = blockIdx.y * 128;
    const int n0 = blockIdx.x * 64;

    const __half* AE = (MODE == 0) ? g_xE : g_attE;
    const __half* BE = (MODE == 0) ? g_wqkvE : g_wprojE;

    float acc[2][4][4];
#pragma unroll
    for (int t = 0; t < 2; t++)
#pragma unroll
        for (int nt = 0; nt < 4; nt++)
#pragma unroll
            for (int j = 0; j < 4; j++) acc[t][nt][j] = 0.f;

    const int li = lane & 7, lg = lane >> 3;
    const uint32_t sAu = s2u(smem_all), sBu = s2u(smem_all + 32768);
    const int rowA0 = wm * 32 + li + (lg & 1) * 8;
    const int chA = lg >> 1;
    const int rowB0 = wn * 32 + li + (lg >> 1) * 8;
    const int chB = lg & 1;

    const int grow = tid >> 3, gseg = tid & 7;

#define GSTAGE(c, buf) { \
        uint32_t aB = sAu + (buf) * 16384; \
        uint32_t bB = sBu + (buf) * 8192;  \
        _Pragma("unroll") \
        for (int it = 0; it < 4; it++) { \
            int row = grow + it * 32; \
            cpasync16(aB + SWZ(row * 128 + gseg * 16), \
                      AE + (size_t)(m0 + row) * KE2 + (c) * 64 + gseg * 8); \
        } \
        _Pragma("unroll") \
        for (int it = 0; it < 2; it++) { \
            int row = grow + it * 32; \
            cpasync16(bB + SWZ(row * 128 + gseg * 16), \
                      BE + (size_t)(n0 + row) * KE2 + (c) * 64 + gseg * 8); \
        } \
        CP_COMMIT(); }

    GSTAGE(0, 0);

    for (int c = 0; c < 6; c++) {
        CP_WAIT0();          // this thread's chunk-c data arrived
        __syncthreads();     // everyone's arrived; everyone done reading buf[(c+1)&1] (iter c-1)
        if (c < 5) GSTAGE(c + 1, (c + 1) & 1);

        uint32_t aB = sAu + (c & 1) * 16384;
        uint32_t bB = sBu + (c & 1) * 8192;
#pragma unroll
        for (int s = 0; s < 4; s++) {
            uint32_t a[2][4], b[2][4];
#pragma unroll
            for (int t = 0; t < 2; t++) {
                int row = rowA0 + t * 16;
                uint32_t addr = aB + row * 128 + (((2 * s + chA) ^ (row & 7)) << 4);
                ldsm4(a[t][0], a[t][1], a[t][2], a[t][3], addr);
            }
#pragma unroll
            for (int p = 0; p < 2; p++) {
                int row = rowB0 + p * 16;
                uint32_t addr = bB + row * 128 + (((2 * s + chB) ^ (row & 7)) << 4);
                ldsm4(b[p][0], b[p][1], b[p][2], b[p][3], addr);
            }
#pragma unroll
            for (int t = 0; t < 2; t++)
#pragma unroll
                for (int nt = 0; nt < 4; nt++)
                    mma16816(acc[t][nt], a[t], &b[nt >> 1][(nt & 1) * 2]);
        }
    }
#undef GSTAGE

    const int nglob = n0 + wn * 32;
    const int qid = lane & 3;
    if (MODE == 0) {
        const int s = nglob / 192;
        const int rem = nglob - s * 192;
        const int h = rem >> 5;
        float mulq = 0.f;
        if (s == 0) mulq = __expf(fminf(lsc[h], 4.605170186f));
#pragma unroll
        for (int t = 0; t < 2; t++) {
#pragma unroll
            for (int half = 0; half < 2; half++) {
                int mrow = m0 + wm * 32 + t * 16 + half * 8 + (lane >> 2);
                float f[8];
#pragma unroll
                for (int nt = 0; nt < 4; nt++) {
                    int d0 = nt * 8 + qid * 2;
                    float b0 = (s == 0) ? bq[rem + d0] : ((s == 2) ? bv[rem + d0] : 0.f);
                    float b1 = (s == 0) ? bq[rem + d0 + 1] : ((s == 2) ? bv[rem + d0 + 1] : 0.f);
                    f[nt * 2 + 0] = acc[t][nt][half * 2 + 0] + b0;
                    f[nt * 2 + 1] = acc[t][nt][half * 2 + 1] + b1;
                }
                float mul = 1.f;
                if (s < 2) {
                    float ss = 0.f;
#pragma unroll
                    for (int j = 0; j < 8; j++) ss = fmaf(f[j], f[j], ss);
                    ss += __shfl_xor_sync(0xffffffffu, ss, 1);
                    ss += __shfl_xor_sync(0xffffffffu, ss, 2);
                    mul = 1.f / fmaxf(sqrtf(ss), 1e-12f);
                    if (s == 0) mul *= mulq;
                }
                const int bb = mrow >> 9, nr = mrow & 511;
                if (s == 0) {
                    float* op = g_q + ((((size_t)bb * HH + h) << 9) + nr) * HD;
#pragma unroll
                    for (int nt = 0; nt < 4; nt++) {
                        int d0 = nt * 8 + qid * 2;
                        *(float2*)(op + d0) = make_float2(f[nt * 2] * mul, f[nt * 2 + 1] * mul);
                    }
                } else {
                    __half* op = (s == 1 ? g_kE : g_vE) +
                                 ((((size_t)bb * HH + h) << 9) + nr) * 32;
#pragma unroll
                    for (int nt = 0; nt < 4; nt++) {
                        int d0 = nt * 8 + qid * 2;
                        *(uint32_t*)(op + d0) = hpack(f[nt * 2] * mul, f[nt * 2 + 1] * mul);
                    }
                }
            }
        }
    } else {
#pragma unroll
        for (int t = 0; t < 2; t++) {
#pragma unroll
            for (int half = 0; half < 2; half++) {
                int mrow = m0 + wm * 32 + t * 16 + half * 8 + (lane >> 2);
                float* op = Cout + (size_t)mrow * CC + nglob;
#pragma unroll
                for (int nt = 0; nt < 4; nt++) {
                    int d0 = nt * 8 + qid * 2;
                    float pb0 = bq[nglob + d0], pb1 = bq[nglob + d0 + 1];
                    *(float2*)(op + d0) = make_float2(acc[t][nt][half * 2 + 0] + pb0,
                                                      acc[t][nt][half * 2 + 1] + pb1);
                }
            }
        }
    }
}

// ---------------- tensor-core flash attention (fp16, cp.async, double-buffered) ----------------
// K/V smem panel: 64 keys x 64B (fp16 hi only), row stride 80B (conflict-free ldsm).
#define PANEL 5120
__global__ void __launch_bounds__(256) attn_mma(const float* __restrict__ mask) {
    const int b = blockIdx.z, h = blockIdx.y;
    const int i0 = blockIdx.x * 128;
    const int w = b & (NWIN - 1);
    const int tid = threadIdx.x, wid = tid >> 5, lane = tid & 31;
    const int qd = lane & 3, r = lane >> 2;

    __shared__ __align__(16) unsigned char sK[2 * PANEL];
    __shared__ __align__(16) unsigned char sV[2 * PANEL];
    const uint32_t sKu = s2u(sK), sVu = s2u(sV);

    const __half* kgE = g_kE + (((size_t)(b * HH + h)) << 9) * 32;
    const __half* vgE = g_vE + (((size_t)(b * HH + h)) << 9) * 32;
    const int crow = tid >> 2, cseg = tid & 3;

#define CPKV(jt, buf) { \
        cpasync16(sKu + (buf) * PANEL + crow * 80 + cseg * 16, \
                  kgE + (size_t)((jt) * 64 + crow) * 32 + cseg * 8); \
        cpasync16(sVu + (buf) * PANEL + crow * 80 + cseg * 16, \
                  vgE + (size_t)((jt) * 64 + crow) * 32 + cseg * 8); \
        CP_COMMIT(); }

    CPKV(0, 0);

    // ---- Q fragments (hi/lo fp16) from fp32 g_q ----
    const int rowg = i0 + wid * 16 + r;
    const float* qrowA = g_q + (((size_t)(b * HH + h) << 9) + rowg) * HD;
    const float* qrowB = qrowA + 8 * HD;
    uint32_t Ahi[2][4], Alo[2][4];
#pragma unroll
    for (int c = 0; c < 2; c++) {
        float2 fa0 = *(const float2*)(qrowA + 2 * qd + 16 * c);
        float2 fb0 = *(const float2*)(qrowB + 2 * qd + 16 * c);
        float2 fa1 = *(const float2*)(qrowA + 2 * qd + 16 * c + 8);
        float2 fb1 = *(const float2*)(qrowB + 2 * qd + 16 * c + 8);
        Ahi[c][0] = hpack(fa0.x, fa0.y); Alo[c][0] = hpack_lo(fa0.x, fa0.y, Ahi[c][0]);
        Ahi[c][1] = hpack(fb0.x, fb0.y); Alo[c][1] = hpack_lo(fb0.x, fb0.y, Ahi[c][1]);
        Ahi[c][2] = hpack(fa1.x, fa1.y); Alo[c][2] = hpack_lo(fa1.x, fa1.y, Ahi[c][2]);
        Ahi[c][3] = hpack(fb1.x, fb1.y); Alo[c][3] = hpack_lo(fb1.x, fb1.y, Ahi[c][3]);
    }

    const int li = lane & 7, lg = lane >> 3;
    const uint32_t kbase = sKu + (((lg >> 1) * 8 + li) * 80) + (lg & 1) * 16;
    const uint32_t vbase = sVu + (((lg & 1) * 8 + li) * 80) + (lg >> 1) * 16;

    const float* pb = g_bias + ((size_t)(h * NT + rowg)) * NT + 2 * qd;
    const float* pm = mask + ((size_t)(w * NT + rowg)) * NT + 2 * qd;

    float O[4][4];
#pragma unroll
    for (int j = 0; j < 4; j++)
#pragma unroll
        for (int u = 0; u < 4; u++) O[j][u] = 0.f;
    float m0v = -1e30f, m1v = -1e30f, lsum0 = 0.f, lsum1 = 0.f;

    for (int jt = 0; jt < 8; jt++) {
        const int buf = jt & 1;
        CP_WAIT0();
        __syncthreads();
        if (jt < 7) CPKV(jt + 1, buf ^ 1);

        // ---- init S with bias + mask ----
        float s[8][4];
#pragma unroll
        for (int j = 0; j < 8; j++) {
            int off = jt * 64 + j * 8;
            float2 bA = *(const float2*)(pb + off);
            float2 bB = *(const float2*)(pb + 8 * NT + off);
            float2 mA = *(const float2*)(pm + off);
            float2 mB = *(const float2*)(pm + 8 * NT + off);
            s[j][0] = bA.x + mA.x; s[j][1] = bA.y + mA.y;
            s[j][2] = bB.x + mB.x; s[j][3] = bB.y + mB.y;
        }

        // ---- S += (qhi+qlo) . khi^T over 64 keys ----
#pragma unroll
        for (int jp = 0; jp < 4; jp++) {
            uint32_t h0[4], h1[4];
            uint32_t base = kbase + buf * PANEL + jp * 16 * 80;
            ldsm4(h0[0], h0[1], h0[2], h0[3], base + 0);
            ldsm4(h1[0], h1[1], h1[2], h1[3], base + 32);
            mma16816(s[2 * jp],     Ahi[0], h0 + 0);  mma16816(s[2 * jp],     Ahi[1], h1 + 0);
            mma16816(s[2 * jp],     Alo[0], h0 + 0);  mma16816(s[2 * jp],     Alo[1], h1 + 0);
            mma16816(s[2 * jp + 1], Ahi[0], h0 + 2);  mma16816(s[2 * jp + 1], Ahi[1], h1 + 2);
            mma16816(s[2 * jp + 1], Alo[0], h0 + 2);  mma16816(s[2 * jp + 1], Alo[1], h1 + 2);
        }

        // ---- online softmax ----
        float tm0 = -1e30f, tm1 = -1e30f;
#pragma unroll
        for (int j = 0; j < 8; j++) {
            tm0 = fmaxf(tm0, fmaxf(s[j][0], s[j][1]));
            tm1 = fmaxf(tm1, fmaxf(s[j][2], s[j][3]));
        }
        tm0 = fmaxf(tm0, __shfl_xor_sync(0xffffffffu, tm0, 1));
        tm0 = fmaxf(tm0, __shfl_xor_sync(0xffffffffu, tm0, 2));
        tm1 = fmaxf(tm1, __shfl_xor_sync(0xffffffffu, tm1, 1));
        tm1 = fmaxf(tm1, __shfl_xor_sync(0xffffffffu, tm1, 2));
        float mn0 = fmaxf(m0v, tm0), mn1 = fmaxf(m1v, tm1);
        float c0 = __expf(m0v - mn0), c1 = __expf(m1v - mn1);
        m0v = mn0; m1v = mn1;
        lsum0 *= c0; lsum1 *= c1;
#pragma unroll
        for (int j = 0; j < 4; j++) {
            O[j][0] *= c0; O[j][1] *= c0; O[j][2] *= c1; O[j][3] *= c1;
        }
#pragma unroll
        for (int j = 0; j < 8; j++) {
            s[j][0] = __expf(s[j][0] - mn0); s[j][1] = __expf(s[j][1] - mn0);
            s[j][2] = __expf(s[j][2] - mn1); s[j][3] = __expf(s[j][3] - mn1);
            lsum0 += s[j][0] + s[j][1];
            lsum1 += s[j][2] + s[j][3];
        }

        // ---- P fragments (hi/lo fp16) ----
        uint32_t Phi[4][4], Plo[4][4];
#pragma unroll
        for (int c = 0; c < 4; c++) {
            Phi[c][0] = hpack(s[2 * c][0], s[2 * c][1]);
            Plo[c][0] = hpack_lo(s[2 * c][0], s[2 * c][1], Phi[c][0]);
            Phi[c][1] = hpack(s[2 * c][2], s[2 * c][3]);
            Plo[c][1] = hpack_lo(s[2 * c][2], s[2 * c][3], Phi[c][1]);
            Phi[c][2] = hpack(s[2 * c + 1][0], s[2 * c + 1][1]);
            Plo[c][2] = hpack_lo(s[2 * c + 1][0], s[2 * c + 1][1], Phi[c][2]);
            Phi[c][3] = hpack(s[2 * c + 1][2], s[2 * c + 1][3]);
            Plo[c][3] = hpack_lo(s[2 * c + 1][2], s[2 * c + 1][3], Phi[c][3]);
        }

        // ---- O += (Phi+Plo) . vhi ----
#pragma unroll
        for (int c = 0; c < 4; c++) {
#pragma unroll
            for (int jd = 0; jd < 2; jd++) {
                uint32_t vh[4];
                uint32_t base = vbase + buf * PANEL + c * 16 * 80 + jd * 32;
                ldsm4t(vh[0], vh[1], vh[2], vh[3], base);
                mma16816(O[2 * jd],     Phi[c], vh + 0);
                mma16816(O[2 * jd],     Plo[c], vh + 0);
                mma16816(O[2 * jd + 1], Phi[c], vh + 2);
                mma16816(O[2 * jd + 1], Plo[c], vh + 2);
            }
        }
    }
#undef CPKV

    // ---- epilogue ----
    lsum0 += __shfl_xor_sync(0xffffffffu, lsum0, 1);
    lsum0 += __shfl_xor_sync(0xffffffffu, lsum0, 2);
    lsum1 += __shfl_xor_sync(0xffffffffu, lsum1, 1);
    lsum1 += __shfl_xor_sync(0xffffffffu, lsum1, 2);
    float inv0 = 1.f / lsum0, inv1 = 1.f / lsum1;

    __half* baseA = g_attE + (size_t)(b * NT + rowg) * KE2 + h * HD + 2 * qd;
    __half* baseB = baseA + (size_t)8 * KE2;
#pragma unroll
    for (int j = 0; j < 4; j++) {
        int col = j * 8;
        uint32_t hiA = hpack(O[j][0] * inv0, O[j][1] * inv0);
        uint32_t loA = hpack_lo(O[j][0] * inv0, O[j][1] * inv0, hiA);
        *(uint32_t*)(baseA + col)      = hiA;
        *(uint32_t*)(baseA + col + CC) = loA;
        uint32_t hiB = hpack(O[j][2] * inv1, O[j][3] * inv1);
        uint32_t loB = hpack_lo(O[j][2] * inv1, O[j][3] * inv1, hiB);
        *(uint32_t*)(baseB + col)      = hiB;
        *(uint32_t*)(baseB + col + CC) = loB;
    }
}

// ---------------- launch ----------------
extern "C" void kernel_launch(void* const* d_in, const int* in_sizes, int n_in,
                              void* d_out, int out_size) {
    const float* x           = (const float*)d_in[0];
    const float* mask        = (const float*)d_in[1];
    const float* qkv_w       = (const float*)d_in[2];
    const float* q_bias      = (const float*)d_in[3];
    const float* v_bias      = (const float*)d_in[4];
    const float* logit_scale = (const float*)d_in[5];
    const float* cpb_w1      = (const float*)d_in[6];
    const float* cpb_b1      = (const float*)d_in[7];
    const float* cpb_w2      = (const float*)d_in[8];
    const float* proj_w      = (const float*)d_in[9];
    const float* proj_b      = (const float*)d_in[10];
    const float* rel_table   = (const float*)d_in[11];
    const int*   rel_index   = (const int*)d_in[12];
    float* out = (float*)d_out;

    cpb_kernel<<<TBL, 128>>>(rel_table, cpb_w1, cpb_b1, cpb_w2);
    prep_kernel<<<NB_XA + NB_WQ + NB_WP + NB_GA, 256>>>(x, qkv_w, proj_w, rel_index);
    mma_gemm<0><<<dim3(9, 256), 256>>>(q_bias, v_bias, logit_scale, nullptr);
    attn_mma<<<dim3(4, HH, BW), 256>>>(mask);
    mma_gemm<1><<<dim3(3, 256), 256>>>(proj_b, nullptr, nullptr, out);
}